// round 3
// baseline (speedup 1.0000x reference)
#include <cuda_runtime.h>
#include <math_constants.h>

#define BATCH 4
#define S_LEN 1024
#define DIM   2048
#define HQ    16
#define HKV   4
#define HD    128
#define MTOT  (BATCH * S_LEN)   // 4096

// Scratch (allocation-free rule: __device__ globals)
__device__ float g_q[MTOT * HQ * HD];    // (4096, 2048)
__device__ float g_k[MTOT * HKV * HD];   // (4096, 512)
__device__ float g_v[MTOT * HKV * HD];   // (4096, 512)
__device__ float g_ao[MTOT * HQ * HD];   // (4096, 2048)

// ---------------------------------------------------------------------------
// SGEMM: C[M,N] = A[M,K] * B[N,K]^T   (both row-major, K contiguous)
// 128x128 block tile, BK=8, 256 threads, 8x8 per thread.
// ---------------------------------------------------------------------------
__global__ void __launch_bounds__(256) sgemm_nt(const float* __restrict__ A,
                                                const float* __restrict__ B,
                                                float* __restrict__ C,
                                                int M, int N, int K) {
    __shared__ float As[8 * 132];
    __shared__ float Bs[8 * 132];

    const int tid = threadIdx.x;
    const int tx = tid & 15;
    const int ty = tid >> 4;
    const int m0 = blockIdx.y * 128;
    const int n0 = blockIdx.x * 128;

    float acc[8][8];
#pragma unroll
    for (int i = 0; i < 8; i++)
#pragma unroll
        for (int j = 0; j < 8; j++) acc[i][j] = 0.0f;

    const int lrow = tid >> 1;        // 0..127
    const int lk   = (tid & 1) * 4;   // 0 or 4
    const float* Ag = A + (size_t)(m0 + lrow) * K + lk;
    const float* Bg = B + (size_t)(n0 + lrow) * K + lk;

    for (int k0 = 0; k0 < K; k0 += 8) {
        float4 av = *(const float4*)(Ag + k0);
        float4 bv = *(const float4*)(Bg + k0);
        As[(lk + 0) * 132 + lrow] = av.x;
        As[(lk + 1) * 132 + lrow] = av.y;
        As[(lk + 2) * 132 + lrow] = av.z;
        As[(lk + 3) * 132 + lrow] = av.w;
        Bs[(lk + 0) * 132 + lrow] = bv.x;
        Bs[(lk + 1) * 132 + lrow] = bv.y;
        Bs[(lk + 2) * 132 + lrow] = bv.z;
        Bs[(lk + 3) * 132 + lrow] = bv.w;
        __syncthreads();

#pragma unroll
        for (int kk = 0; kk < 8; kk++) {
            float4 a0 = *(const float4*)&As[kk * 132 + ty * 4];
            float4 a1 = *(const float4*)&As[kk * 132 + 64 + ty * 4];
            float4 b0 = *(const float4*)&Bs[kk * 132 + tx * 4];
            float4 b1 = *(const float4*)&Bs[kk * 132 + 64 + tx * 4];
            float a[8] = {a0.x, a0.y, a0.z, a0.w, a1.x, a1.y, a1.z, a1.w};
            float b[8] = {b0.x, b0.y, b0.z, b0.w, b1.x, b1.y, b1.z, b1.w};
#pragma unroll
            for (int i = 0; i < 8; i++)
#pragma unroll
                for (int j = 0; j < 8; j++) acc[i][j] = fmaf(a[i], b[j], acc[i][j]);
        }
        __syncthreads();
    }

#pragma unroll
    for (int i = 0; i < 8; i++) {
        int r = m0 + ((i < 4) ? (ty * 4 + i) : (64 + ty * 4 + i - 4));
        float4 c0 = make_float4(acc[i][0], acc[i][1], acc[i][2], acc[i][3]);
        float4 c1 = make_float4(acc[i][4], acc[i][5], acc[i][6], acc[i][7]);
        *(float4*)&C[(size_t)r * N + n0 + tx * 4]      = c0;
        *(float4*)&C[(size_t)r * N + n0 + 64 + tx * 4] = c1;
    }
}

// ---------------------------------------------------------------------------
// RoPE (Llama-style adjacent pairs): in-place on (MTOT, nheads*HD)
// ---------------------------------------------------------------------------
__global__ void rope_kernel(float* __restrict__ t, const float* __restrict__ freqs,
                            int nheads, int total_pairs) {
    int idx = blockIdx.x * blockDim.x + threadIdx.x;
    if (idx >= total_pairs) return;
    int p = idx & (HD / 2 - 1);            // 0..63
    int h = (idx >> 6) % nheads;
    int m = idx / ((HD / 2) * nheads);
    int s = m & (S_LEN - 1);
    float ang = freqs[s * (HD / 2) + p];
    float c = cosf(ang), sn = sinf(ang);
    float* base = t + (size_t)m * nheads * HD + h * HD + 2 * p;
    float x0 = base[0], x1 = base[1];
    base[0] = x0 * c - x1 * sn;
    base[1] = x0 * sn + x1 * c;
}

// ---------------------------------------------------------------------------
// Flash attention fp32, causal, GQA. One CTA = 64 query rows of one (b, qh).
// 256 threads as (16 ty rows-groups) x (16 tx col-groups); 4x4 score tile each.
// ---------------------------------------------------------------------------
__global__ void __launch_bounds__(256) attn_kernel(const float* __restrict__ q,
                                                   const float* __restrict__ k,
                                                   const float* __restrict__ v,
                                                   float* __restrict__ o) {
    extern __shared__ float sm[];
    float* Qs = sm;            // 64*128
    float* Ks = sm + 8192;     // 64*128
    float* Vs = sm + 16384;    // 64*128
    float* Ps = sm + 24576;    // 64*64

    const int tid = threadIdx.x;
    const int tx = tid & 15;
    const int ty = tid >> 4;
    const int qt = blockIdx.x;      // query tile (64 rows)
    const int qh = blockIdx.y;      // query head
    const int b  = blockIdx.z;
    const int kh = qh >> 2;         // GQA: G = HQ/HKV = 4
    const int q0 = qt * 64;

    const float scale = 0.08838834764831845f;  // 1/sqrt(128)

    // Load Q tile (64 x 128)
    const float* qbase = q + ((size_t)(b * S_LEN + q0)) * (HQ * HD) + qh * HD;
    for (int u = tid; u < 2048; u += 256) {
        int row = u >> 5, c4 = (u & 31) * 4;
        *(float4*)&Qs[row * 128 + c4] =
            *(const float4*)&qbase[(size_t)row * (HQ * HD) + c4];
    }

    float acc[4][8];
#pragma unroll
    for (int i = 0; i < 4; i++)
#pragma unroll
        for (int j = 0; j < 8; j++) acc[i][j] = 0.0f;
    float mi[4] = {-CUDART_INF_F, -CUDART_INF_F, -CUDART_INF_F, -CUDART_INF_F};
    float li[4] = {0.0f, 0.0f, 0.0f, 0.0f};

    for (int kt = 0; kt <= qt; kt++) {
        const int t0 = kt * 64;
        __syncthreads();  // previous PV done before overwriting K/V
        const float* kbase = k + ((size_t)(b * S_LEN + t0)) * (HKV * HD) + kh * HD;
        const float* vbase = v + ((size_t)(b * S_LEN + t0)) * (HKV * HD) + kh * HD;
        for (int u = tid; u < 2048; u += 256) {
            int row = u >> 5, c4 = (u & 31) * 4;
            *(float4*)&Ks[row * 128 + c4] =
                *(const float4*)&kbase[(size_t)row * (HKV * HD) + c4];
            *(float4*)&Vs[row * 128 + c4] =
                *(const float4*)&vbase[(size_t)row * (HKV * HD) + c4];
        }
        __syncthreads();

        // Scores: S = Q K^T  (4x4 per thread)
        float s[4][4];
#pragma unroll
        for (int i = 0; i < 4; i++)
#pragma unroll
            for (int j = 0; j < 4; j++) s[i][j] = 0.0f;

#pragma unroll 4
        for (int kk = 0; kk < 128; kk += 4) {
            float4 qv[4], kv[4];
#pragma unroll
            for (int i = 0; i < 4; i++)
                qv[i] = *(const float4*)&Qs[(ty * 4 + i) * 128 + kk];
#pragma unroll
            for (int j = 0; j < 4; j++)
                kv[j] = *(const float4*)&Ks[(tx * 4 + j) * 128 + kk];
#pragma unroll
            for (int i = 0; i < 4; i++)
#pragma unroll
                for (int j = 0; j < 4; j++) {
                    s[i][j] = fmaf(qv[i].x, kv[j].x, s[i][j]);
                    s[i][j] = fmaf(qv[i].y, kv[j].y, s[i][j]);
                    s[i][j] = fmaf(qv[i].z, kv[j].z, s[i][j]);
                    s[i][j] = fmaf(qv[i].w, kv[j].w, s[i][j]);
                }
        }

        const bool diag = (kt == qt);
#pragma unroll
        for (int i = 0; i < 4; i++) {
#pragma unroll
            for (int j = 0; j < 4; j++) {
                float sc = s[i][j] * scale;
                if (diag && (t0 + tx * 4 + j) > (q0 + ty * 4 + i)) sc += -1e9f;
                s[i][j] = sc;
            }
            // row max across this thread's 4 cols, then across 16 tx lanes
            float mx = fmaxf(fmaxf(s[i][0], s[i][1]), fmaxf(s[i][2], s[i][3]));
#pragma unroll
            for (int off = 8; off; off >>= 1)
                mx = fmaxf(mx, __shfl_xor_sync(0xffffffffu, mx, off));
            float mnew = fmaxf(mi[i], mx);
            float al = __expf(mi[i] - mnew);
            float rs = 0.0f;
#pragma unroll
            for (int j = 0; j < 4; j++) {
                float pv = __expf(s[i][j] - mnew);
                s[i][j] = pv;
                rs += pv;
            }
#pragma unroll
            for (int off = 8; off; off >>= 1)
                rs += __shfl_xor_sync(0xffffffffu, rs, off);
            li[i] = li[i] * al + rs;
            mi[i] = mnew;
#pragma unroll
            for (int jj = 0; jj < 8; jj++) acc[i][jj] *= al;
#pragma unroll
            for (int j = 0; j < 4; j++)
                Ps[(ty * 4 + i) * 64 + tx * 4 + j] = s[i][j];
        }
        __syncthreads();

        // O += P @ V  (rows ty*4+i, cols tx*4.. and 64+tx*4..)
#pragma unroll 4
        for (int c = 0; c < 64; c++) {
            float4 va = *(const float4*)&Vs[c * 128 + tx * 4];
            float4 vb = *(const float4*)&Vs[c * 128 + 64 + tx * 4];
#pragma unroll
            for (int i = 0; i < 4; i++) {
                float p = Ps[(ty * 4 + i) * 64 + c];
                acc[i][0] = fmaf(p, va.x, acc[i][0]);
                acc[i][1] = fmaf(p, va.y, acc[i][1]);
                acc[i][2] = fmaf(p, va.z, acc[i][2]);
                acc[i][3] = fmaf(p, va.w, acc[i][3]);
                acc[i][4] = fmaf(p, vb.x, acc[i][4]);
                acc[i][5] = fmaf(p, vb.y, acc[i][5]);
                acc[i][6] = fmaf(p, vb.z, acc[i][6]);
                acc[i][7] = fmaf(p, vb.w, acc[i][7]);
            }
        }
    }

    // Normalize and store
    float* obase = o + ((size_t)(b * S_LEN + q0)) * (HQ * HD) + qh * HD;
#pragma unroll
    for (int i = 0; i < 4; i++) {
        float inv = 1.0f / li[i];
        float4 r0 = make_float4(acc[i][0] * inv, acc[i][1] * inv,
                                acc[i][2] * inv, acc[i][3] * inv);
        float4 r1 = make_float4(acc[i][4] * inv, acc[i][5] * inv,
                                acc[i][6] * inv, acc[i][7] * inv);
        *(float4*)&obase[(size_t)(ty * 4 + i) * (HQ * HD) + tx * 4]      = r0;
        *(float4*)&obase[(size_t)(ty * 4 + i) * (HQ * HD) + 64 + tx * 4] = r1;
    }
}

// ---------------------------------------------------------------------------
// Launch
// ---------------------------------------------------------------------------
extern "C" void kernel_launch(void* const* d_in, const int* in_sizes, int n_in,
                              void* d_out, int out_size) {
    const float* x     = (const float*)d_in[0];
    // d_in[1] = start_pos (0, unused)
    const float* freqs = (const float*)d_in[2];
    // d_in[3] = mask (equivalent to causal -1e9, applied analytically)
    const float* wq    = (const float*)d_in[4];
    const float* wk    = (const float*)d_in[5];
    const float* wv    = (const float*)d_in[6];
    const float* wo    = (const float*)d_in[7];
    float* out = (float*)d_out;

    float *qb, *kb, *vb, *aob;
    cudaGetSymbolAddress((void**)&qb,  g_q);
    cudaGetSymbolAddress((void**)&kb,  g_k);
    cudaGetSymbolAddress((void**)&vb,  g_v);
    cudaGetSymbolAddress((void**)&aob, g_ao);

    // QKV projections
    sgemm_nt<<<dim3(DIM / 128, MTOT / 128), 256>>>(x, wq, qb, MTOT, HQ * HD, DIM);
    sgemm_nt<<<dim3((HKV * HD) / 128, MTOT / 128), 256>>>(x, wk, kb, MTOT, HKV * HD, DIM);
    sgemm_nt<<<dim3((HKV * HD) / 128, MTOT / 128), 256>>>(x, wv, vb, MTOT, HKV * HD, DIM);

    // RoPE on q and k
    {
        int tp_q = MTOT * HQ * (HD / 2);
        int tp_k = MTOT * HKV * (HD / 2);
        rope_kernel<<<(tp_q + 255) / 256, 256>>>(qb, freqs, HQ, tp_q);
        rope_kernel<<<(tp_k + 255) / 256, 256>>>(kb, freqs, HKV, tp_k);
    }

    // Attention
    {
        int smem = (8192 * 3 + 4096) * (int)sizeof(float);  // 114688 B
        cudaFuncSetAttribute(attn_kernel, cudaFuncAttributeMaxDynamicSharedMemorySize, smem);
        attn_kernel<<<dim3(S_LEN / 64, HQ, BATCH), 256, smem>>>(qb, kb, vb, aob);
    }

    // Output projection
    sgemm_nt<<<dim3(DIM / 128, MTOT / 128), 256>>>(aob, wo, out, MTOT, DIM, DIM);
}

// round 6
// speedup vs baseline: 1.6912x; 1.6912x over previous
#include <cuda_runtime.h>
#include <math_constants.h>
#include <cstdint>

#define BATCH 4
#define S_LEN 1024
#define DIM   2048
#define HQ    16
#define HKV   4
#define HD    128
#define MTOT  (BATCH * S_LEN)   // 4096

// Scratch (allocation-free rule: __device__ globals)
__device__ float g_q[MTOT * HQ * HD];    // (4096, 2048)
__device__ float g_k[MTOT * HKV * HD];   // (4096, 512)
__device__ float g_v[MTOT * HKV * HD];   // (4096, 512)
__device__ float g_ao[MTOT * HQ * HD];   // (4096, 2048)

// ===========================================================================
// Helpers (PTX available on non-arch-specific compute_103 target)
// ===========================================================================
__device__ __forceinline__ void cp_async16(uint32_t dst, const float* src) {
    asm volatile("cp.async.cg.shared.global [%0], [%1], 16;\n"
                 :: "r"(dst), "l"(__cvta_generic_to_global(src)));
}
#define CP_COMMIT() asm volatile("cp.async.commit_group;\n" ::: "memory")
#define CP_WAIT0()  asm volatile("cp.async.wait_group 0;\n" ::: "memory")
#define CP_WAIT1()  asm volatile("cp.async.wait_group 1;\n" ::: "memory")

__device__ __forceinline__ uint32_t f2tf32(float x) {
    uint32_t r;
    asm("cvt.rna.tf32.f32 %0, %1;" : "=r"(r) : "f"(x));
    return r;
}

// D += A*B  (m16n8k8 tf32)
__device__ __forceinline__ void mma_tf32(float* c, const uint32_t* a,
                                         const uint32_t* b) {
    asm volatile(
        "mma.sync.aligned.m16n8k8.row.col.f32.tf32.tf32.f32 "
        "{%0,%1,%2,%3}, {%4,%5,%6,%7}, {%8,%9}, {%0,%1,%2,%3};"
        : "+f"(c[0]), "+f"(c[1]), "+f"(c[2]), "+f"(c[3])
        : "r"(a[0]), "r"(a[1]), "r"(a[2]), "r"(a[3]), "r"(b[0]), "r"(b[1]));
}

// ===========================================================================
// tf32 mma.sync GEMM: C[M,N] = A[M,K] * B[N,K]^T  (row-major, K contiguous)
// CTA tile 128x128, BK=32, 256 threads (8 warps, 64x32 warp tile),
// double-buffered cp.async. smem rows padded to 36 floats (conflict-free).
// ===========================================================================
#define SA 36                       // smem row stride in floats
#define TILE_WORDS (128 * SA)       // 4608 floats = 18432 B per buffer
#define GEMM_SMEM (4 * TILE_WORDS * 4)  // A0,A1,B0,B1 = 73728 B

__device__ __forceinline__ void load_tile_pair(float* smA, float* smB,
                                               const float* A, const float* B,
                                               int K, int m0, int n0, int k0,
                                               int tid) {
    const int r  = tid >> 1;           // 0..127
    const int cb = (tid & 1) * 16;     // float col base (0 or 16)
    const float* asrc = A + (size_t)(m0 + r) * K + k0 + cb;
    const float* bsrc = B + (size_t)(n0 + r) * K + k0 + cb;
    uint32_t da = (uint32_t)__cvta_generic_to_shared(smA + r * SA + cb);
    uint32_t db = (uint32_t)__cvta_generic_to_shared(smB + r * SA + cb);
#pragma unroll
    for (int j = 0; j < 4; j++) {
        cp_async16(da + j * 16, asrc + j * 4);
        cp_async16(db + j * 16, bsrc + j * 4);
    }
}

__device__ __forceinline__ void gemm_core(float* smem, const float* A,
                                          const float* B, float* C,
                                          int N, int K, int m0, int n0) {
    const int tid = threadIdx.x;
    const int wid = tid >> 5;
    const int lane = tid & 31;
    const int g   = lane >> 2;   // 0..7
    const int tig = lane & 3;    // 0..3
    const int wm = wid >> 2;     // 0..1 -> m offset wm*64
    const int wn = wid & 3;      // 0..3 -> n offset wn*32

    float* A0 = smem;
    float* A1 = smem + TILE_WORDS;
    float* B0 = smem + 2 * TILE_WORDS;
    float* B1 = smem + 3 * TILE_WORDS;

    float c[4][4][4];
#pragma unroll
    for (int i = 0; i < 4; i++)
#pragma unroll
        for (int j = 0; j < 4; j++)
#pragma unroll
            for (int q = 0; q < 4; q++) c[i][j][q] = 0.0f;

    const int NK = K >> 5;

    load_tile_pair(A0, B0, A, B, K, m0, n0, 0, tid);
    CP_COMMIT();

    for (int kt = 0; kt < NK; kt++) {
        if (kt + 1 < NK) {
            load_tile_pair((kt & 1) ? A0 : A1, (kt & 1) ? B0 : B1,
                           A, B, K, m0, n0, (kt + 1) * 32, tid);
            CP_COMMIT();
            CP_WAIT1();
        } else {
            CP_WAIT0();
        }
        __syncthreads();

        const float* As = (kt & 1) ? A1 : A0;
        const float* Bs = (kt & 1) ? B1 : B0;

#pragma unroll
        for (int kk = 0; kk < 4; kk++) {
            uint32_t af[4][4], bf[4][2];
#pragma unroll
            for (int ma = 0; ma < 4; ma++) {
                const float* p = As + (wm * 64 + ma * 16 + g) * SA + kk * 8 + tig;
                af[ma][0] = f2tf32(p[0]);
                af[ma][2] = f2tf32(p[4]);
                af[ma][1] = f2tf32(p[8 * SA]);
                af[ma][3] = f2tf32(p[8 * SA + 4]);
            }
#pragma unroll
            for (int nb = 0; nb < 4; nb++) {
                const float* p = Bs + (wn * 32 + nb * 8 + g) * SA + kk * 8 + tig;
                bf[nb][0] = f2tf32(p[0]);
                bf[nb][1] = f2tf32(p[4]);
            }
#pragma unroll
            for (int ma = 0; ma < 4; ma++)
#pragma unroll
                for (int nb = 0; nb < 4; nb++)
                    mma_tf32(c[ma][nb], af[ma], bf[nb]);
        }
        __syncthreads();
    }

    // Epilogue: c[ma][nb] is 16x8 at rows m0+wm*64+ma*16+{g,g+8},
    // cols n0+wn*32+nb*8+{2*tig, 2*tig+1}
#pragma unroll
    for (int ma = 0; ma < 4; ma++) {
        const int r0 = m0 + wm * 64 + ma * 16 + g;
#pragma unroll
        for (int nb = 0; nb < 4; nb++) {
            const int col = n0 + wn * 32 + nb * 8 + 2 * tig;
            *(float2*)&C[(size_t)r0 * N + col] = make_float2(c[ma][nb][0], c[ma][nb][1]);
            *(float2*)&C[(size_t)(r0 + 8) * N + col] = make_float2(c[ma][nb][2], c[ma][nb][3]);
        }
    }
}

// Fused QKV: grid.x = 16 (wq) + 4 (wk) + 4 (wv) n-tiles, grid.y = 32 m-tiles.
__global__ void __launch_bounds__(256, 2) gemm_qkv_kernel(
    const float* __restrict__ x, const float* __restrict__ wq,
    const float* __restrict__ wk, const float* __restrict__ wv,
    float* __restrict__ q, float* __restrict__ k, float* __restrict__ v) {
    extern __shared__ float smem[];
    const int bx = blockIdx.x;
    const int m0 = blockIdx.y * 128;
    const float* B; float* C; int N, n0;
    if (bx < 16)      { B = wq; C = q; N = 2048; n0 = bx * 128; }
    else if (bx < 20) { B = wk; C = k; N = 512;  n0 = (bx - 16) * 128; }
    else              { B = wv; C = v; N = 512;  n0 = (bx - 20) * 128; }
    gemm_core(smem, x, B, C, N, DIM, m0, n0);
}

// Generic: grid (N/128, M/128)
__global__ void __launch_bounds__(256, 2) gemm_tf32_kernel(
    const float* __restrict__ A, const float* __restrict__ B,
    float* __restrict__ C, int N, int K) {
    extern __shared__ float smem[];
    gemm_core(smem, A, B, C, N, K, blockIdx.y * 128, blockIdx.x * 128);
}

// ---------------------------------------------------------------------------
// RoPE (Llama-style adjacent pairs): in-place on (MTOT, nheads*HD)
// ---------------------------------------------------------------------------
__global__ void rope_kernel(float* __restrict__ t, const float* __restrict__ freqs,
                            int nheads, int total_pairs) {
    int idx = blockIdx.x * blockDim.x + threadIdx.x;
    if (idx >= total_pairs) return;
    int p = idx & (HD / 2 - 1);            // 0..63
    int h = (idx >> 6) % nheads;
    int m = idx / ((HD / 2) * nheads);
    int s = m & (S_LEN - 1);
    float ang = freqs[s * (HD / 2) + p];
    float c = cosf(ang), sn = sinf(ang);
    float* base = t + (size_t)m * nheads * HD + h * HD + 2 * p;
    float x0 = base[0], x1 = base[1];
    base[0] = x0 * c - x1 * sn;
    base[1] = x0 * sn + x1 * c;
}

// ---------------------------------------------------------------------------
// Flash attention fp32, causal, GQA. One CTA = 64 query rows of one (b, qh).
// ---------------------------------------------------------------------------
__global__ void __launch_bounds__(256) attn_kernel(const float* __restrict__ q,
                                                   const float* __restrict__ k,
                                                   const float* __restrict__ v,
                                                   float* __restrict__ o) {
    extern __shared__ float sm[];
    float* Qs = sm;            // 64*128
    float* Ks = sm + 8192;     // 64*128
    float* Vs = sm + 16384;    // 64*128
    float* Ps = sm + 24576;    // 64*64

    const int tid = threadIdx.x;
    const int tx = tid & 15;
    const int ty = tid >> 4;
    const int qt = blockIdx.x;      // query tile (64 rows)
    const int qh = blockIdx.y;      // query head
    const int b  = blockIdx.z;
    const int kh = qh >> 2;         // GQA: G = HQ/HKV = 4
    const int q0 = qt * 64;

    const float scale = 0.08838834764831845f;  // 1/sqrt(128)

    const float* qbase = q + ((size_t)(b * S_LEN + q0)) * (HQ * HD) + qh * HD;
    for (int u = tid; u < 2048; u += 256) {
        int row = u >> 5, c4 = (u & 31) * 4;
        *(float4*)&Qs[row * 128 + c4] =
            *(const float4*)&qbase[(size_t)row * (HQ * HD) + c4];
    }

    float acc[4][8];
#pragma unroll
    for (int i = 0; i < 4; i++)
#pragma unroll
        for (int j = 0; j < 8; j++) acc[i][j] = 0.0f;
    float mi[4] = {-CUDART_INF_F, -CUDART_INF_F, -CUDART_INF_F, -CUDART_INF_F};
    float li[4] = {0.0f, 0.0f, 0.0f, 0.0f};

    for (int kt = 0; kt <= qt; kt++) {
        const int t0 = kt * 64;
        __syncthreads();
        const float* kbase = k + ((size_t)(b * S_LEN + t0)) * (HKV * HD) + kh * HD;
        const float* vbase = v + ((size_t)(b * S_LEN + t0)) * (HKV * HD) + kh * HD;
        for (int u = tid; u < 2048; u += 256) {
            int row = u >> 5, c4 = (u & 31) * 4;
            *(float4*)&Ks[row * 128 + c4] =
                *(const float4*)&kbase[(size_t)row * (HKV * HD) + c4];
            *(float4*)&Vs[row * 128 + c4] =
                *(const float4*)&vbase[(size_t)row * (HKV * HD) + c4];
        }
        __syncthreads();

        float s[4][4];
#pragma unroll
        for (int i = 0; i < 4; i++)
#pragma unroll
            for (int j = 0; j < 4; j++) s[i][j] = 0.0f;

#pragma unroll 4
        for (int kk = 0; kk < 128; kk += 4) {
            float4 qv[4], kv[4];
#pragma unroll
            for (int i = 0; i < 4; i++)
                qv[i] = *(const float4*)&Qs[(ty * 4 + i) * 128 + kk];
#pragma unroll
            for (int j = 0; j < 4; j++)
                kv[j] = *(const float4*)&Ks[(tx * 4 + j) * 128 + kk];
#pragma unroll
            for (int i = 0; i < 4; i++)
#pragma unroll
                for (int j = 0; j < 4; j++) {
                    s[i][j] = fmaf(qv[i].x, kv[j].x, s[i][j]);
                    s[i][j] = fmaf(qv[i].y, kv[j].y, s[i][j]);
                    s[i][j] = fmaf(qv[i].z, kv[j].z, s[i][j]);
                    s[i][j] = fmaf(qv[i].w, kv[j].w, s[i][j]);
                }
        }

        const bool diag = (kt == qt);
#pragma unroll
        for (int i = 0; i < 4; i++) {
#pragma unroll
            for (int j = 0; j < 4; j++) {
                float sc = s[i][j] * scale;
                if (diag && (t0 + tx * 4 + j) > (q0 + ty * 4 + i)) sc += -1e9f;
                s[i][j] = sc;
            }
            float mx = fmaxf(fmaxf(s[i][0], s[i][1]), fmaxf(s[i][2], s[i][3]));
#pragma unroll
            for (int off = 8; off; off >>= 1)
                mx = fmaxf(mx, __shfl_xor_sync(0xffffffffu, mx, off));
            float mnew = fmaxf(mi[i], mx);
            float al = __expf(mi[i] - mnew);
            float rs = 0.0f;
#pragma unroll
            for (int j = 0; j < 4; j++) {
                float pv = __expf(s[i][j] - mnew);
                s[i][j] = pv;
                rs += pv;
            }
#pragma unroll
            for (int off = 8; off; off >>= 1)
                rs += __shfl_xor_sync(0xffffffffu, rs, off);
            li[i] = li[i] * al + rs;
            mi[i] = mnew;
#pragma unroll
            for (int jj = 0; jj < 8; jj++) acc[i][jj] *= al;
#pragma unroll
            for (int j = 0; j < 4; j++)
                Ps[(ty * 4 + i) * 64 + tx * 4 + j] = s[i][j];
        }
        __syncthreads();

#pragma unroll 4
        for (int c = 0; c < 64; c++) {
            float4 va = *(const float4*)&Vs[c * 128 + tx * 4];
            float4 vb = *(const float4*)&Vs[c * 128 + 64 + tx * 4];
#pragma unroll
            for (int i = 0; i < 4; i++) {
                float p = Ps[(ty * 4 + i) * 64 + c];
                acc[i][0] = fmaf(p, va.x, acc[i][0]);
                acc[i][1] = fmaf(p, va.y, acc[i][1]);
                acc[i][2] = fmaf(p, va.z, acc[i][2]);
                acc[i][3] = fmaf(p, va.w, acc[i][3]);
                acc[i][4] = fmaf(p, vb.x, acc[i][4]);
                acc[i][5] = fmaf(p, vb.y, acc[i][5]);
                acc[i][6] = fmaf(p, vb.z, acc[i][6]);
                acc[i][7] = fmaf(p, vb.w, acc[i][7]);
            }
        }
    }

    float* obase = o + ((size_t)(b * S_LEN + q0)) * (HQ * HD) + qh * HD;
#pragma unroll
    for (int i = 0; i < 4; i++) {
        float inv = 1.0f / li[i];
        float4 r0 = make_float4(acc[i][0] * inv, acc[i][1] * inv,
                                acc[i][2] * inv, acc[i][3] * inv);
        float4 r1 = make_float4(acc[i][4] * inv, acc[i][5] * inv,
                                acc[i][6] * inv, acc[i][7] * inv);
        *(float4*)&obase[(size_t)(ty * 4 + i) * (HQ * HD) + tx * 4]      = r0;
        *(float4*)&obase[(size_t)(ty * 4 + i) * (HQ * HD) + 64 + tx * 4] = r1;
    }
}

// ---------------------------------------------------------------------------
// Launch
// ---------------------------------------------------------------------------
extern "C" void kernel_launch(void* const* d_in, const int* in_sizes, int n_in,
                              void* d_out, int out_size) {
    const float* x     = (const float*)d_in[0];
    const float* freqs = (const float*)d_in[2];
    const float* wq    = (const float*)d_in[4];
    const float* wk    = (const float*)d_in[5];
    const float* wv    = (const float*)d_in[6];
    const float* wo    = (const float*)d_in[7];
    float* out = (float*)d_out;

    float *qb, *kb, *vb, *aob;
    cudaGetSymbolAddress((void**)&qb,  g_q);
    cudaGetSymbolAddress((void**)&kb,  g_k);
    cudaGetSymbolAddress((void**)&vb,  g_v);
    cudaGetSymbolAddress((void**)&aob, g_ao);

    static bool attr_done = false;
    if (!attr_done) {
        cudaFuncSetAttribute(gemm_qkv_kernel,
                             cudaFuncAttributeMaxDynamicSharedMemorySize, GEMM_SMEM);
        cudaFuncSetAttribute(gemm_tf32_kernel,
                             cudaFuncAttributeMaxDynamicSharedMemorySize, GEMM_SMEM);
        cudaFuncSetAttribute(attn_kernel,
                             cudaFuncAttributeMaxDynamicSharedMemorySize, 114688);
        attr_done = true;
    }

    // Fused QKV projections (mma.sync tf32)
    gemm_qkv_kernel<<<dim3(24, MTOT / 128), 256, GEMM_SMEM>>>(
        x, wq, wk, wv, qb, kb, vb);

    // RoPE on q and k
    {
        int tp_q = MTOT * HQ * (HD / 2);
        int tp_k = MTOT * HKV * (HD / 2);
        rope_kernel<<<(tp_q + 255) / 256, 256>>>(qb, freqs, HQ, tp_q);
        rope_kernel<<<(tp_k + 255) / 256, 256>>>(kb, freqs, HKV, tp_k);
    }

    // Attention (fp32 flash, unchanged this round)
    attn_kernel<<<dim3(S_LEN / 64, HQ, BATCH), 256, 114688>>>(qb, kb, vb, aob);

    // Output projection (mma.sync tf32)
    gemm_tf32_kernel<<<dim3(DIM / 128, MTOT / 128), 256, GEMM_SMEM>>>(
        aob, wo, out, DIM, DIM);
}

// round 10
// speedup vs baseline: 3.7264x; 2.2035x over previous
#include <cuda_runtime.h>
#include <math_constants.h>
#include <cstdint>

#define BATCH 4
#define S_LEN 1024
#define DIM   2048
#define HQ    16
#define HKV   4
#define HD    128
#define MTOT  (BATCH * S_LEN)   // 4096

// Scratch (allocation-free rule: __device__ globals)
__device__ float g_q[MTOT * HQ * HD];    // (4096, 2048)
__device__ float g_k[MTOT * HKV * HD];   // (4096, 512)
__device__ float g_v[MTOT * HKV * HD];   // (4096, 512)
__device__ float g_ao[MTOT * HQ * HD];   // (4096, 2048)

// ===========================================================================
// Helpers (PTX available on non-arch-specific compute_103 target)
// ===========================================================================
__device__ __forceinline__ void cp_async16(uint32_t dst, const float* src) {
    asm volatile("cp.async.cg.shared.global [%0], [%1], 16;\n"
                 :: "r"(dst), "l"(__cvta_generic_to_global(src)));
}
#define CP_COMMIT() asm volatile("cp.async.commit_group;\n" ::: "memory")
#define CP_WAIT0()  asm volatile("cp.async.wait_group 0;\n" ::: "memory")
#define CP_WAIT1()  asm volatile("cp.async.wait_group 1;\n" ::: "memory")

__device__ __forceinline__ uint32_t f2tf32(float x) {
    uint32_t r;
    asm("cvt.rna.tf32.f32 %0, %1;" : "=r"(r) : "f"(x));
    return r;
}
__device__ __forceinline__ float f2tf32f(float x) {
    return __uint_as_float(f2tf32(x));
}

// D += A*B  (m16n8k8 tf32)
__device__ __forceinline__ void mma_tf32(float* c, const uint32_t* a,
                                         const uint32_t* b) {
    asm volatile(
        "mma.sync.aligned.m16n8k8.row.col.f32.tf32.tf32.f32 "
        "{%0,%1,%2,%3}, {%4,%5,%6,%7}, {%8,%9}, {%0,%1,%2,%3};"
        : "+f"(c[0]), "+f"(c[1]), "+f"(c[2]), "+f"(c[3])
        : "r"(a[0]), "r"(a[1]), "r"(a[2]), "r"(a[3]), "r"(b[0]), "r"(b[1]));
}

// ===========================================================================
// tf32 mma.sync GEMM: C[M,N] = A[M,K] * B[N,K]^T  (row-major, K contiguous)
// ===========================================================================
#define SA 36
#define TILE_WORDS (128 * SA)
#define GEMM_SMEM (4 * TILE_WORDS * 4)

__device__ __forceinline__ void load_tile_pair(float* smA, float* smB,
                                               const float* A, const float* B,
                                               int K, int m0, int n0, int k0,
                                               int tid) {
    const int r  = tid >> 1;
    const int cb = (tid & 1) * 16;
    const float* asrc = A + (size_t)(m0 + r) * K + k0 + cb;
    const float* bsrc = B + (size_t)(n0 + r) * K + k0 + cb;
    uint32_t da = (uint32_t)__cvta_generic_to_shared(smA + r * SA + cb);
    uint32_t db = (uint32_t)__cvta_generic_to_shared(smB + r * SA + cb);
#pragma unroll
    for (int j = 0; j < 4; j++) {
        cp_async16(da + j * 16, asrc + j * 4);
        cp_async16(db + j * 16, bsrc + j * 4);
    }
}

__device__ __forceinline__ void gemm_core(float* smem, const float* A,
                                          const float* B, float* C,
                                          int N, int K, int m0, int n0) {
    const int tid = threadIdx.x;
    const int wid = tid >> 5;
    const int lane = tid & 31;
    const int g   = lane >> 2;
    const int tig = lane & 3;
    const int wm = wid >> 2;
    const int wn = wid & 3;

    float* A0 = smem;
    float* A1 = smem + TILE_WORDS;
    float* B0 = smem + 2 * TILE_WORDS;
    float* B1 = smem + 3 * TILE_WORDS;

    float c[4][4][4];
#pragma unroll
    for (int i = 0; i < 4; i++)
#pragma unroll
        for (int j = 0; j < 4; j++)
#pragma unroll
            for (int q = 0; q < 4; q++) c[i][j][q] = 0.0f;

    const int NK = K >> 5;

    load_tile_pair(A0, B0, A, B, K, m0, n0, 0, tid);
    CP_COMMIT();

    for (int kt = 0; kt < NK; kt++) {
        if (kt + 1 < NK) {
            load_tile_pair((kt & 1) ? A0 : A1, (kt & 1) ? B0 : B1,
                           A, B, K, m0, n0, (kt + 1) * 32, tid);
            CP_COMMIT();
            CP_WAIT1();
        } else {
            CP_WAIT0();
        }
        __syncthreads();

        const float* As = (kt & 1) ? A1 : A0;
        const float* Bs = (kt & 1) ? B1 : B0;

#pragma unroll
        for (int kk = 0; kk < 4; kk++) {
            uint32_t af[4][4], bf[4][2];
#pragma unroll
            for (int ma = 0; ma < 4; ma++) {
                const float* p = As + (wm * 64 + ma * 16 + g) * SA + kk * 8 + tig;
                af[ma][0] = f2tf32(p[0]);
                af[ma][2] = f2tf32(p[4]);
                af[ma][1] = f2tf32(p[8 * SA]);
                af[ma][3] = f2tf32(p[8 * SA + 4]);
            }
#pragma unroll
            for (int nb = 0; nb < 4; nb++) {
                const float* p = Bs + (wn * 32 + nb * 8 + g) * SA + kk * 8 + tig;
                bf[nb][0] = f2tf32(p[0]);
                bf[nb][1] = f2tf32(p[4]);
            }
#pragma unroll
            for (int ma = 0; ma < 4; ma++)
#pragma unroll
                for (int nb = 0; nb < 4; nb++)
                    mma_tf32(c[ma][nb], af[ma], bf[nb]);
        }
        __syncthreads();
    }

#pragma unroll
    for (int ma = 0; ma < 4; ma++) {
        const int r0 = m0 + wm * 64 + ma * 16 + g;
#pragma unroll
        for (int nb = 0; nb < 4; nb++) {
            const int col = n0 + wn * 32 + nb * 8 + 2 * tig;
            *(float2*)&C[(size_t)r0 * N + col] = make_float2(c[ma][nb][0], c[ma][nb][1]);
            *(float2*)&C[(size_t)(r0 + 8) * N + col] = make_float2(c[ma][nb][2], c[ma][nb][3]);
        }
    }
}

__global__ void __launch_bounds__(256, 2) gemm_qkv_kernel(
    const float* __restrict__ x, const float* __restrict__ wq,
    const float* __restrict__ wk, const float* __restrict__ wv,
    float* __restrict__ q, float* __restrict__ k, float* __restrict__ v) {
    extern __shared__ float smem[];
    const int bx = blockIdx.x;
    const int m0 = blockIdx.y * 128;
    const float* B; float* C; int N, n0;
    if (bx < 16)      { B = wq; C = q; N = 2048; n0 = bx * 128; }
    else if (bx < 20) { B = wk; C = k; N = 512;  n0 = (bx - 16) * 128; }
    else              { B = wv; C = v; N = 512;  n0 = (bx - 20) * 128; }
    gemm_core(smem, x, B, C, N, DIM, m0, n0);
}

__global__ void __launch_bounds__(256, 2) gemm_tf32_kernel(
    const float* __restrict__ A, const float* __restrict__ B,
    float* __restrict__ C, int N, int K) {
    extern __shared__ float smem[];
    gemm_core(smem, A, B, C, N, K, blockIdx.y * 128, blockIdx.x * 128);
}

// ---------------------------------------------------------------------------
// RoPE (Llama-style adjacent pairs): in-place on (MTOT, nheads*HD)
// ---------------------------------------------------------------------------
__global__ void rope_kernel(float* __restrict__ t, const float* __restrict__ freqs,
                            int nheads, int total_pairs) {
    int idx = blockIdx.x * blockDim.x + threadIdx.x;
    if (idx >= total_pairs) return;
    int p = idx & (HD / 2 - 1);
    int h = (idx >> 6) % nheads;
    int m = idx / ((HD / 2) * nheads);
    int s = m & (S_LEN - 1);
    float ang = freqs[s * (HD / 2) + p];
    float c = cosf(ang), sn = sinf(ang);
    float* base = t + (size_t)m * nheads * HD + h * HD + 2 * p;
    float x0 = base[0], x1 = base[1];
    base[0] = x0 * c - x1 * sn;
    base[1] = x0 * sn + x1 * c;
}

// ===========================================================================
// Tensorized flash attention (mma.sync tf32), causal, GQA.
// CTA = 128 q-rows of one (b, qh). 8 warps x 16-row m-blocks. KV tile 64.
// smem: Qs[128][132], Ks[64][132], VsT[128][68] (V transposed), Ps[8][16][68]
// ===========================================================================
#define QS_STRIDE 132
#define VT_STRIDE 68
#define PS_STRIDE 68
#define ATTN_SMEM ((128 * 132 + 64 * 132 + 128 * 68 + 8 * 16 * 68) * 4)  // 171008

__global__ void __launch_bounds__(256, 1) attn_mma_kernel(
    const float* __restrict__ q, const float* __restrict__ k,
    const float* __restrict__ v, float* __restrict__ o) {
    extern __shared__ float sm[];
    float* Qs  = sm;                     // 128*132
    float* Ks  = Qs + 128 * QS_STRIDE;   // 64*132
    float* VsT = Ks + 64 * QS_STRIDE;    // 128*68 [d][t]
    float* Ps  = VsT + 128 * VT_STRIDE;  // per-warp 16*68

    const int tid  = threadIdx.x;
    const int lane = tid & 31;
    const int wid  = tid >> 5;
    const int g    = lane >> 2;
    const int tig  = lane & 3;
    const int qt = blockIdx.x;
    const int qh = blockIdx.y;
    const int b  = blockIdx.z;
    const int kh = qh >> 2;
    const int q0 = qt * 128;
    const int wm0 = wid * 16;

    const float scale = 0.08838834764831845f;  // 1/sqrt(128)

    // ---- Load Q tile (tf32-rounded) ----
    const float* qp = q + ((size_t)(b * S_LEN + q0)) * (HQ * HD) + qh * HD;
#pragma unroll
    for (int it = 0; it < 16; it++) {
        int row = it * 8 + (tid >> 5);
        int c4  = (tid & 31) * 4;
        float4 val = *(const float4*)&qp[(size_t)row * (HQ * HD) + c4];
        float4 ot = make_float4(f2tf32f(val.x), f2tf32f(val.y),
                                f2tf32f(val.z), f2tf32f(val.w));
        *(float4*)&Qs[row * QS_STRIDE + c4] = ot;
    }

    float oacc[16][4];
#pragma unroll
    for (int nf = 0; nf < 16; nf++)
#pragma unroll
        for (int j = 0; j < 4; j++) oacc[nf][j] = 0.0f;
    float mi[2] = {-CUDART_INF_F, -CUDART_INF_F};
    float li[2] = {0.0f, 0.0f};

    const int nkt = 2 * qt + 2;
    for (int kt = 0; kt < nkt; kt++) {
        const int t0 = kt * 64;
        __syncthreads();   // previous iter's Ks/VsT reads complete

        // ---- Load K tile (64 x 128, tf32) ----
        const float* kp = k + ((size_t)(b * S_LEN + t0)) * (HKV * HD) + kh * HD;
#pragma unroll
        for (int it = 0; it < 8; it++) {
            int row = it * 8 + (tid >> 5);
            int c4  = (tid & 31) * 4;
            float4 val = *(const float4*)&kp[(size_t)row * (HKV * HD) + c4];
            float4 ot = make_float4(f2tf32f(val.x), f2tf32f(val.y),
                                    f2tf32f(val.z), f2tf32f(val.w));
            *(float4*)&Ks[row * QS_STRIDE + c4] = ot;
        }
        // ---- Load V tile transposed: VsT[d][t] (tf32) ----
        const float* vp = v + ((size_t)(b * S_LEN + t0)) * (HKV * HD) + kh * HD;
#pragma unroll
        for (int it = 0; it < 8; it++) {
            int idx = it * 256 + tid;
            int grp = idx >> 5;                   // uniform per warp
            int t4  = (grp & 15) * 4;
            int d   = (grp >> 4) * 32 + (idx & 31);
            float a0 = vp[(size_t)(t4 + 0) * (HKV * HD) + d];
            float a1 = vp[(size_t)(t4 + 1) * (HKV * HD) + d];
            float a2 = vp[(size_t)(t4 + 2) * (HKV * HD) + d];
            float a3 = vp[(size_t)(t4 + 3) * (HKV * HD) + d];
            *(float4*)&VsT[d * VT_STRIDE + t4] =
                make_float4(f2tf32f(a0), f2tf32f(a1), f2tf32f(a2), f2tf32f(a3));
        }
        __syncthreads();

        // Skip fully-masked warp tiles (t0 beyond this warp's last row)
        if (t0 > q0 + wm0 + 15) continue;

        // ---- S = Q K^T (16 x 64 per warp) ----
        float s[8][4];
#pragma unroll
        for (int nb = 0; nb < 8; nb++)
#pragma unroll
            for (int j = 0; j < 4; j++) s[nb][j] = 0.0f;

#pragma unroll
        for (int kk = 0; kk < 16; kk++) {
            const float* ap = Qs + (wm0 + g) * QS_STRIDE + kk * 8 + tig;
            uint32_t af[4];
            af[0] = *(const uint32_t*)&ap[0];
            af[1] = *(const uint32_t*)&ap[8 * QS_STRIDE];
            af[2] = *(const uint32_t*)&ap[4];
            af[3] = *(const uint32_t*)&ap[8 * QS_STRIDE + 4];
#pragma unroll
            for (int nb = 0; nb < 8; nb++) {
                const float* bp = Ks + (nb * 8 + g) * QS_STRIDE + kk * 8 + tig;
                uint32_t bf[2];
                bf[0] = *(const uint32_t*)&bp[0];
                bf[1] = *(const uint32_t*)&bp[4];
                mma_tf32(s[nb], af, bf);
            }
        }

        // ---- Scale + causal mask ----
        const int row0 = q0 + wm0 + g;
#pragma unroll
        for (int nb = 0; nb < 8; nb++) {
#pragma unroll
            for (int j = 0; j < 4; j++) {
                int col = t0 + nb * 8 + 2 * tig + (j & 1);
                int row = row0 + ((j >= 2) ? 8 : 0);
                float sc = s[nb][j] * scale;
                s[nb][j] = (col > row) ? -1e9f : sc;
            }
        }

        // ---- Online softmax (rows g and g+8 per lane) ----
#pragma unroll
        for (int h = 0; h < 2; h++) {
            float mx = -CUDART_INF_F;
#pragma unroll
            for (int nb = 0; nb < 8; nb++)
                mx = fmaxf(mx, fmaxf(s[nb][2 * h], s[nb][2 * h + 1]));
            mx = fmaxf(mx, __shfl_xor_sync(0xffffffffu, mx, 1));
            mx = fmaxf(mx, __shfl_xor_sync(0xffffffffu, mx, 2));
            float mnew = fmaxf(mi[h], mx);
            float al = __expf(mi[h] - mnew);
            float rs = 0.0f;
#pragma unroll
            for (int nb = 0; nb < 8; nb++) {
                float p0 = __expf(s[nb][2 * h] - mnew);
                float p1 = __expf(s[nb][2 * h + 1] - mnew);
                s[nb][2 * h] = p0;
                s[nb][2 * h + 1] = p1;
                rs += p0 + p1;
            }
            rs += __shfl_xor_sync(0xffffffffu, rs, 1);
            rs += __shfl_xor_sync(0xffffffffu, rs, 2);
            li[h] = li[h] * al + rs;
            mi[h] = mnew;
#pragma unroll
            for (int nf = 0; nf < 16; nf++) {
                oacc[nf][2 * h]     *= al;
                oacc[nf][2 * h + 1] *= al;
            }
        }

        // ---- Store P (tf32) to per-warp smem ----
        float* Pw = Ps + wid * 16 * PS_STRIDE;
#pragma unroll
        for (int nb = 0; nb < 8; nb++) {
            *(float2*)&Pw[g * PS_STRIDE + nb * 8 + 2 * tig] =
                make_float2(f2tf32f(s[nb][0]), f2tf32f(s[nb][1]));
            *(float2*)&Pw[(g + 8) * PS_STRIDE + nb * 8 + 2 * tig] =
                make_float2(f2tf32f(s[nb][2]), f2tf32f(s[nb][3]));
        }
        __syncwarp();

        // ---- O += P V  (16 x 128 per warp) ----
#pragma unroll
        for (int kk = 0; kk < 8; kk++) {
            const float* ap = Pw + g * PS_STRIDE + kk * 8 + tig;
            uint32_t af[4];
            af[0] = *(const uint32_t*)&ap[0];
            af[1] = *(const uint32_t*)&ap[8 * PS_STRIDE];
            af[2] = *(const uint32_t*)&ap[4];
            af[3] = *(const uint32_t*)&ap[8 * PS_STRIDE + 4];
#pragma unroll
            for (int nf = 0; nf < 16; nf++) {
                const float* bp = VsT + (nf * 8 + g) * VT_STRIDE + kk * 8 + tig;
                uint32_t bf[2];
                bf[0] = *(const uint32_t*)&bp[0];
                bf[1] = *(const uint32_t*)&bp[4];
                mma_tf32(oacc[nf], af, bf);
            }
        }
        __syncwarp();   // Pw reads done before next iter's overwrite
    }

    // ---- Normalize + store ----
    const float inv0 = 1.0f / li[0];
    const float inv1 = 1.0f / li[1];
    float* ob = o + ((size_t)(b * S_LEN + q0 + wm0 + g)) * (HQ * HD) + qh * HD;
#pragma unroll
    for (int nf = 0; nf < 16; nf++) {
        int col = nf * 8 + 2 * tig;
        *(float2*)&ob[col] = make_float2(oacc[nf][0] * inv0, oacc[nf][1] * inv0);
        *(float2*)&ob[(size_t)8 * (HQ * HD) + col] =
            make_float2(oacc[nf][2] * inv1, oacc[nf][3] * inv1);
    }
}

// ---------------------------------------------------------------------------
// Launch
// ---------------------------------------------------------------------------
extern "C" void kernel_launch(void* const* d_in, const int* in_sizes, int n_in,
                              void* d_out, int out_size) {
    const float* x     = (const float*)d_in[0];
    const float* freqs = (const float*)d_in[2];
    const float* wq    = (const float*)d_in[4];
    const float* wk    = (const float*)d_in[5];
    const float* wv    = (const float*)d_in[6];
    const float* wo    = (const float*)d_in[7];
    float* out = (float*)d_out;

    float *qb, *kb, *vb, *aob;
    cudaGetSymbolAddress((void**)&qb,  g_q);
    cudaGetSymbolAddress((void**)&kb,  g_k);
    cudaGetSymbolAddress((void**)&vb,  g_v);
    cudaGetSymbolAddress((void**)&aob, g_ao);

    static bool attr_done = false;
    if (!attr_done) {
        cudaFuncSetAttribute(gemm_qkv_kernel,
                             cudaFuncAttributeMaxDynamicSharedMemorySize, GEMM_SMEM);
        cudaFuncSetAttribute(gemm_tf32_kernel,
                             cudaFuncAttributeMaxDynamicSharedMemorySize, GEMM_SMEM);
        cudaFuncSetAttribute(attn_mma_kernel,
                             cudaFuncAttributeMaxDynamicSharedMemorySize, ATTN_SMEM);
        attr_done = true;
    }

    // Fused QKV projections (mma.sync tf32)
    gemm_qkv_kernel<<<dim3(24, MTOT / 128), 256, GEMM_SMEM>>>(
        x, wq, wk, wv, qb, kb, vb);

    // RoPE on q and k
    {
        int tp_q = MTOT * HQ * (HD / 2);
        int tp_k = MTOT * HKV * (HD / 2);
        rope_kernel<<<(tp_q + 255) / 256, 256>>>(qb, freqs, HQ, tp_q);
        rope_kernel<<<(tp_k + 255) / 256, 256>>>(kb, freqs, HKV, tp_k);
    }

    // Attention (mma.sync tf32 flash)
    attn_mma_kernel<<<dim3(S_LEN / 128, HQ, BATCH), 256, ATTN_SMEM>>>(
        qb, kb, vb, aob);

    // Output projection (mma.sync tf32)
    gemm_tf32_kernel<<<dim3(DIM / 128, MTOT / 128), 256, GEMM_SMEM>>>(
        aob, wo, out, DIM, DIM);
}

// round 11
// speedup vs baseline: 3.8118x; 1.0229x over previous
#include <cuda_runtime.h>
#include <math_constants.h>
#include <cstdint>

#define BATCH 4
#define S_LEN 1024
#define DIM   2048
#define HQ    16
#define HKV   4
#define HD    128
#define MTOT  (BATCH * S_LEN)   // 4096

// Scratch (allocation-free rule: __device__ globals)
__device__ float g_q[MTOT * HQ * HD];     // (4096, 2048) fp32
__device__ float g_k[MTOT * HKV * HD];    // (4096, 512)  fp32
__device__ float g_v[MTOT * HKV * HD];    // (4096, 512)  fp32
__device__ float g_xp[MTOT * DIM];        // x, tf32+permuted
__device__ float g_wqp[DIM * DIM];        // wq, tf32+permuted
__device__ float g_wkp[HKV * HD * DIM];   // wk, tf32+permuted
__device__ float g_wvp[HKV * HD * DIM];   // wv, tf32+permuted
__device__ float g_wop[DIM * DIM];        // wo, tf32+permuted
__device__ float g_aop[MTOT * DIM];       // attn out, tf32+permuted

// ===========================================================================
// Helpers (PTX available on non-arch-specific compute_103 target)
// ===========================================================================
__device__ __forceinline__ void cp_async16(uint32_t dst, const float* src) {
    asm volatile("cp.async.cg.shared.global [%0], [%1], 16;\n"
                 :: "r"(dst), "l"(__cvta_generic_to_global(src)));
}
#define CP_COMMIT() asm volatile("cp.async.commit_group;\n" ::: "memory")
#define CP_WAIT0()  asm volatile("cp.async.wait_group 0;\n" ::: "memory")
#define CP_WAIT1()  asm volatile("cp.async.wait_group 1;\n" ::: "memory")

__device__ __forceinline__ uint32_t f2tf32(float x) {
    uint32_t r;
    asm("cvt.rna.tf32.f32 %0, %1;" : "=r"(r) : "f"(x));
    return r;
}
__device__ __forceinline__ float f2tf32f(float x) {
    return __uint_as_float(f2tf32(x));
}

// D += A*B  (m16n8k8 tf32)
__device__ __forceinline__ void mma_tf32(float* c, const uint32_t* a,
                                         const uint32_t* b) {
    asm volatile(
        "mma.sync.aligned.m16n8k8.row.col.f32.tf32.tf32.f32 "
        "{%0,%1,%2,%3}, {%4,%5,%6,%7}, {%8,%9}, {%0,%1,%2,%3};"
        : "+f"(c[0]), "+f"(c[1]), "+f"(c[2]), "+f"(c[3])
        : "r"(a[0]), "r"(a[1]), "r"(a[2]), "r"(a[3]), "r"(b[0]), "r"(b[1]));
}

// ===========================================================================
// Pre-pass: tf32-round + K-permute (groups of 8: new[2j]=old[j], new[2j+1]=old[j+4])
// One thread per 8-float group. Coalesced read and write.
// ===========================================================================
__global__ void prep_kernel(const float* __restrict__ in, float* __restrict__ out,
                            int n8) {
    int i = blockIdx.x * blockDim.x + threadIdx.x;
    if (i >= n8) return;
    const float4* p = (const float4*)(in + (size_t)i * 8);
    float4 a = p[0], b = p[1];
    float4* q = (float4*)(out + (size_t)i * 8);
    q[0] = make_float4(f2tf32f(a.x), f2tf32f(b.x), f2tf32f(a.y), f2tf32f(b.y));
    q[1] = make_float4(f2tf32f(a.z), f2tf32f(b.z), f2tf32f(a.w), f2tf32f(b.w));
}

// ===========================================================================
// tf32 mma.sync GEMM on pre-rounded, K-permuted operands.
// C[M,N] = A[M,K] * B[N,K]^T. CTA tile 128x128, BK=32, 8 warps (64x32 each).
// Smem stride 40 floats -> LDS.64 fragment loads are bank-conflict-free.
// ===========================================================================
#define SA 40
#define TILE_WORDS (128 * SA)               // 5120 floats
#define GEMM_SMEM (4 * TILE_WORDS * 4)      // 81920 B

__device__ __forceinline__ void load_tile_pair(float* smA, float* smB,
                                               const float* A, const float* B,
                                               int K, int m0, int n0, int k0,
                                               int tid) {
    const int r  = tid >> 1;
    const int cb = (tid & 1) * 16;
    const float* asrc = A + (size_t)(m0 + r) * K + k0 + cb;
    const float* bsrc = B + (size_t)(n0 + r) * K + k0 + cb;
    uint32_t da = (uint32_t)__cvta_generic_to_shared(smA + r * SA + cb);
    uint32_t db = (uint32_t)__cvta_generic_to_shared(smB + r * SA + cb);
#pragma unroll
    for (int j = 0; j < 4; j++) {
        cp_async16(da + j * 16, asrc + j * 4);
        cp_async16(db + j * 16, bsrc + j * 4);
    }
}

__device__ __forceinline__ void gemm_core(float* smem, const float* A,
                                          const float* B, float* C,
                                          int N, int K, int m0, int n0) {
    const int tid = threadIdx.x;
    const int wid = tid >> 5;
    const int lane = tid & 31;
    const int g   = lane >> 2;
    const int tig = lane & 3;
    const int wm = wid >> 2;
    const int wn = wid & 3;

    float* A0 = smem;
    float* A1 = smem + TILE_WORDS;
    float* B0 = smem + 2 * TILE_WORDS;
    float* B1 = smem + 3 * TILE_WORDS;

    float c[4][4][4];
#pragma unroll
    for (int i = 0; i < 4; i++)
#pragma unroll
        for (int j = 0; j < 4; j++)
#pragma unroll
            for (int q = 0; q < 4; q++) c[i][j][q] = 0.0f;

    const int NK = K >> 5;

    load_tile_pair(A0, B0, A, B, K, m0, n0, 0, tid);
    CP_COMMIT();

    for (int kt = 0; kt < NK; kt++) {
        if (kt + 1 < NK) {
            load_tile_pair((kt & 1) ? A0 : A1, (kt & 1) ? B0 : B1,
                           A, B, K, m0, n0, (kt + 1) * 32, tid);
            CP_COMMIT();
            CP_WAIT1();
        } else {
            CP_WAIT0();
        }
        __syncthreads();

        const float* As = (kt & 1) ? A1 : A0;
        const float* Bs = (kt & 1) ? B1 : B0;

#pragma unroll
        for (int kk = 0; kk < 4; kk++) {
            uint32_t af[4][4], bf[4][2];
#pragma unroll
            for (int ma = 0; ma < 4; ma++) {
                const float* p = As + (wm * 64 + ma * 16 + g) * SA + kk * 8 + 2 * tig;
                float2 lo = *(const float2*)p;
                float2 hi = *(const float2*)(p + 8 * SA);
                af[ma][0] = __float_as_uint(lo.x);
                af[ma][2] = __float_as_uint(lo.y);
                af[ma][1] = __float_as_uint(hi.x);
                af[ma][3] = __float_as_uint(hi.y);
            }
#pragma unroll
            for (int nb = 0; nb < 4; nb++) {
                const float* p = Bs + (wn * 32 + nb * 8 + g) * SA + kk * 8 + 2 * tig;
                float2 v = *(const float2*)p;
                bf[nb][0] = __float_as_uint(v.x);
                bf[nb][1] = __float_as_uint(v.y);
            }
#pragma unroll
            for (int ma = 0; ma < 4; ma++)
#pragma unroll
                for (int nb = 0; nb < 4; nb++)
                    mma_tf32(c[ma][nb], af[ma], bf[nb]);
        }
        __syncthreads();
    }

#pragma unroll
    for (int ma = 0; ma < 4; ma++) {
        const int r0 = m0 + wm * 64 + ma * 16 + g;
#pragma unroll
        for (int nb = 0; nb < 4; nb++) {
            const int col = n0 + wn * 32 + nb * 8 + 2 * tig;
            *(float2*)&C[(size_t)r0 * N + col] = make_float2(c[ma][nb][0], c[ma][nb][1]);
            *(float2*)&C[(size_t)(r0 + 8) * N + col] = make_float2(c[ma][nb][2], c[ma][nb][3]);
        }
    }
}

__global__ void __launch_bounds__(256, 2) gemm_qkv_kernel(
    const float* __restrict__ x, const float* __restrict__ wq,
    const float* __restrict__ wk, const float* __restrict__ wv,
    float* __restrict__ q, float* __restrict__ k, float* __restrict__ v) {
    extern __shared__ float smem[];
    const int bx = blockIdx.x;
    const int m0 = blockIdx.y * 128;
    const float* B; float* C; int N, n0;
    if (bx < 16)      { B = wq; C = q; N = 2048; n0 = bx * 128; }
    else if (bx < 20) { B = wk; C = k; N = 512;  n0 = (bx - 16) * 128; }
    else              { B = wv; C = v; N = 512;  n0 = (bx - 20) * 128; }
    gemm_core(smem, x, B, C, N, DIM, m0, n0);
}

__global__ void __launch_bounds__(256, 2) gemm_tf32_kernel(
    const float* __restrict__ A, const float* __restrict__ B,
    float* __restrict__ C, int N, int K) {
    extern __shared__ float smem[];
    gemm_core(smem, A, B, C, N, K, blockIdx.y * 128, blockIdx.x * 128);
}

// ---------------------------------------------------------------------------
// RoPE (Llama-style adjacent pairs): in-place on (MTOT, nheads*HD)
// ---------------------------------------------------------------------------
__global__ void rope_kernel(float* __restrict__ t, const float* __restrict__ freqs,
                            int nheads, int total_pairs) {
    int idx = blockIdx.x * blockDim.x + threadIdx.x;
    if (idx >= total_pairs) return;
    int p = idx & (HD / 2 - 1);
    int h = (idx >> 6) % nheads;
    int m = idx / ((HD / 2) * nheads);
    int s = m & (S_LEN - 1);
    float ang = freqs[s * (HD / 2) + p];
    float c = cosf(ang), sn = sinf(ang);
    float* base = t + (size_t)m * nheads * HD + h * HD + 2 * p;
    float x0 = base[0], x1 = base[1];
    base[0] = x0 * c - x1 * sn;
    base[1] = x0 * sn + x1 * c;
}

// ===========================================================================
// Tensorized flash attention (mma.sync tf32), causal, GQA.
// CTA = 128 q-rows of one (b, qh). 8 warps x 16-row m-blocks. KV tile 64.
// Output written tf32-rounded + K-permuted straight into g_aop.
// ===========================================================================
#define QS_STRIDE 132
#define VT_STRIDE 68
#define PS_STRIDE 68
#define ATTN_SMEM ((128 * 132 + 64 * 132 + 128 * 68 + 8 * 16 * 68) * 4)  // 171008

__global__ void __launch_bounds__(256, 1) attn_mma_kernel(
    const float* __restrict__ q, const float* __restrict__ k,
    const float* __restrict__ v, float* __restrict__ o) {
    extern __shared__ float sm[];
    float* Qs  = sm;                     // 128*132
    float* Ks  = Qs + 128 * QS_STRIDE;   // 64*132
    float* VsT = Ks + 64 * QS_STRIDE;    // 128*68 [d][t]
    float* Ps  = VsT + 128 * VT_STRIDE;  // per-warp 16*68

    const int tid  = threadIdx.x;
    const int lane = tid & 31;
    const int wid  = tid >> 5;
    const int g    = lane >> 2;
    const int tig  = lane & 3;
    const int qt = blockIdx.x;
    const int qh = blockIdx.y;
    const int b  = blockIdx.z;
    const int kh = qh >> 2;
    const int q0 = qt * 128;
    const int wm0 = wid * 16;

    const float scale = 0.08838834764831845f;  // 1/sqrt(128)

    // ---- Load Q tile (tf32-rounded) ----
    const float* qp = q + ((size_t)(b * S_LEN + q0)) * (HQ * HD) + qh * HD;
#pragma unroll
    for (int it = 0; it < 16; it++) {
        int row = it * 8 + (tid >> 5);
        int c4  = (tid & 31) * 4;
        float4 val = *(const float4*)&qp[(size_t)row * (HQ * HD) + c4];
        float4 ot = make_float4(f2tf32f(val.x), f2tf32f(val.y),
                                f2tf32f(val.z), f2tf32f(val.w));
        *(float4*)&Qs[row * QS_STRIDE + c4] = ot;
    }

    float oacc[16][4];
#pragma unroll
    for (int nf = 0; nf < 16; nf++)
#pragma unroll
        for (int j = 0; j < 4; j++) oacc[nf][j] = 0.0f;
    float mi[2] = {-CUDART_INF_F, -CUDART_INF_F};
    float li[2] = {0.0f, 0.0f};

    const int nkt = 2 * qt + 2;
    for (int kt = 0; kt < nkt; kt++) {
        const int t0 = kt * 64;
        __syncthreads();

        const float* kp = k + ((size_t)(b * S_LEN + t0)) * (HKV * HD) + kh * HD;
#pragma unroll
        for (int it = 0; it < 8; it++) {
            int row = it * 8 + (tid >> 5);
            int c4  = (tid & 31) * 4;
            float4 val = *(const float4*)&kp[(size_t)row * (HKV * HD) + c4];
            float4 ot = make_float4(f2tf32f(val.x), f2tf32f(val.y),
                                    f2tf32f(val.z), f2tf32f(val.w));
            *(float4*)&Ks[row * QS_STRIDE + c4] = ot;
        }
        const float* vp = v + ((size_t)(b * S_LEN + t0)) * (HKV * HD) + kh * HD;
#pragma unroll
        for (int it = 0; it < 8; it++) {
            int idx = it * 256 + tid;
            int grp = idx >> 5;
            int t4  = (grp & 15) * 4;
            int d   = (grp >> 4) * 32 + (idx & 31);
            float a0 = vp[(size_t)(t4 + 0) * (HKV * HD) + d];
            float a1 = vp[(size_t)(t4 + 1) * (HKV * HD) + d];
            float a2 = vp[(size_t)(t4 + 2) * (HKV * HD) + d];
            float a3 = vp[(size_t)(t4 + 3) * (HKV * HD) + d];
            *(float4*)&VsT[d * VT_STRIDE + t4] =
                make_float4(f2tf32f(a0), f2tf32f(a1), f2tf32f(a2), f2tf32f(a3));
        }
        __syncthreads();

        if (t0 > q0 + wm0 + 15) continue;

        float s[8][4];
#pragma unroll
        for (int nb = 0; nb < 8; nb++)
#pragma unroll
            for (int j = 0; j < 4; j++) s[nb][j] = 0.0f;

#pragma unroll
        for (int kk = 0; kk < 16; kk++) {
            const float* ap = Qs + (wm0 + g) * QS_STRIDE + kk * 8 + tig;
            uint32_t af[4];
            af[0] = *(const uint32_t*)&ap[0];
            af[1] = *(const uint32_t*)&ap[8 * QS_STRIDE];
            af[2] = *(const uint32_t*)&ap[4];
            af[3] = *(const uint32_t*)&ap[8 * QS_STRIDE + 4];
#pragma unroll
            for (int nb = 0; nb < 8; nb++) {
                const float* bp = Ks + (nb * 8 + g) * QS_STRIDE + kk * 8 + tig;
                uint32_t bf[2];
                bf[0] = *(const uint32_t*)&bp[0];
                bf[1] = *(const uint32_t*)&bp[4];
                mma_tf32(s[nb], af, bf);
            }
        }

        const int row0 = q0 + wm0 + g;
#pragma unroll
        for (int nb = 0; nb < 8; nb++) {
#pragma unroll
            for (int j = 0; j < 4; j++) {
                int col = t0 + nb * 8 + 2 * tig + (j & 1);
                int row = row0 + ((j >= 2) ? 8 : 0);
                float sc = s[nb][j] * scale;
                s[nb][j] = (col > row) ? -1e9f : sc;
            }
        }

#pragma unroll
        for (int h = 0; h < 2; h++) {
            float mx = -CUDART_INF_F;
#pragma unroll
            for (int nb = 0; nb < 8; nb++)
                mx = fmaxf(mx, fmaxf(s[nb][2 * h], s[nb][2 * h + 1]));
            mx = fmaxf(mx, __shfl_xor_sync(0xffffffffu, mx, 1));
            mx = fmaxf(mx, __shfl_xor_sync(0xffffffffu, mx, 2));
            float mnew = fmaxf(mi[h], mx);
            float al = __expf(mi[h] - mnew);
            float rs = 0.0f;
#pragma unroll
            for (int nb = 0; nb < 8; nb++) {
                float p0 = __expf(s[nb][2 * h] - mnew);
                float p1 = __expf(s[nb][2 * h + 1] - mnew);
                s[nb][2 * h] = p0;
                s[nb][2 * h + 1] = p1;
                rs += p0 + p1;
            }
            rs += __shfl_xor_sync(0xffffffffu, rs, 1);
            rs += __shfl_xor_sync(0xffffffffu, rs, 2);
            li[h] = li[h] * al + rs;
            mi[h] = mnew;
#pragma unroll
            for (int nf = 0; nf < 16; nf++) {
                oacc[nf][2 * h]     *= al;
                oacc[nf][2 * h + 1] *= al;
            }
        }

        float* Pw = Ps + wid * 16 * PS_STRIDE;
#pragma unroll
        for (int nb = 0; nb < 8; nb++) {
            *(float2*)&Pw[g * PS_STRIDE + nb * 8 + 2 * tig] =
                make_float2(f2tf32f(s[nb][0]), f2tf32f(s[nb][1]));
            *(float2*)&Pw[(g + 8) * PS_STRIDE + nb * 8 + 2 * tig] =
                make_float2(f2tf32f(s[nb][2]), f2tf32f(s[nb][3]));
        }
        __syncwarp();

#pragma unroll
        for (int kk = 0; kk < 8; kk++) {
            const float* ap = Pw + g * PS_STRIDE + kk * 8 + tig;
            uint32_t af[4];
            af[0] = *(const uint32_t*)&ap[0];
            af[1] = *(const uint32_t*)&ap[8 * PS_STRIDE];
            af[2] = *(const uint32_t*)&ap[4];
            af[3] = *(const uint32_t*)&ap[8 * PS_STRIDE + 4];
#pragma unroll
            for (int nf = 0; nf < 16; nf++) {
                const float* bp = VsT + (nf * 8 + g) * VT_STRIDE + kk * 8 + tig;
                uint32_t bf[2];
                bf[0] = *(const uint32_t*)&bp[0];
                bf[1] = *(const uint32_t*)&bp[4];
                mma_tf32(oacc[nf], af, bf);
            }
        }
        __syncwarp();
    }

    // ---- Normalize + store tf32-rounded, K-PERMUTED (for wo GEMM A operand) ----
    // Lane holds old cols {2tig, 2tig+1} of each 8-group; permuted positions:
    // old c<4 -> 2c ; old c>=4 -> 2(c-4)+1  =>  cols {e, e+2}, e = tig<2 ? 4tig : 4tig-7
    const float inv0 = 1.0f / li[0];
    const float inv1 = 1.0f / li[1];
    const int e = (tig < 2) ? 4 * tig : 4 * tig - 7;
    float* ob = o + ((size_t)(b * S_LEN + q0 + wm0 + g)) * (HQ * HD) + qh * HD;
#pragma unroll
    for (int nf = 0; nf < 16; nf++) {
        int base = nf * 8;
        ob[base + e]     = f2tf32f(oacc[nf][0] * inv0);
        ob[base + e + 2] = f2tf32f(oacc[nf][1] * inv0);
        ob[(size_t)8 * (HQ * HD) + base + e]     = f2tf32f(oacc[nf][2] * inv1);
        ob[(size_t)8 * (HQ * HD) + base + e + 2] = f2tf32f(oacc[nf][3] * inv1);
    }
}

// ---------------------------------------------------------------------------
// Launch
// ---------------------------------------------------------------------------
extern "C" void kernel_launch(void* const* d_in, const int* in_sizes, int n_in,
                              void* d_out, int out_size) {
    const float* x     = (const float*)d_in[0];
    const float* freqs = (const float*)d_in[2];
    const float* wq    = (const float*)d_in[4];
    const float* wk    = (const float*)d_in[5];
    const float* wv    = (const float*)d_in[6];
    const float* wo    = (const float*)d_in[7];
    float* out = (float*)d_out;

    float *qb, *kb, *vb, *xp, *wqp, *wkp, *wvp, *wop, *aop;
    cudaGetSymbolAddress((void**)&qb,  g_q);
    cudaGetSymbolAddress((void**)&kb,  g_k);
    cudaGetSymbolAddress((void**)&vb,  g_v);
    cudaGetSymbolAddress((void**)&xp,  g_xp);
    cudaGetSymbolAddress((void**)&wqp, g_wqp);
    cudaGetSymbolAddress((void**)&wkp, g_wkp);
    cudaGetSymbolAddress((void**)&wvp, g_wvp);
    cudaGetSymbolAddress((void**)&wop, g_wop);
    cudaGetSymbolAddress((void**)&aop, g_aop);

    static bool attr_done = false;
    if (!attr_done) {
        cudaFuncSetAttribute(gemm_qkv_kernel,
                             cudaFuncAttributeMaxDynamicSharedMemorySize, GEMM_SMEM);
        cudaFuncSetAttribute(gemm_tf32_kernel,
                             cudaFuncAttributeMaxDynamicSharedMemorySize, GEMM_SMEM);
        cudaFuncSetAttribute(attn_mma_kernel,
                             cudaFuncAttributeMaxDynamicSharedMemorySize, ATTN_SMEM);
        attr_done = true;
    }

    // Pre-pass: tf32 round + K-permute all GEMM operands
    {
        int n;
        n = MTOT * DIM / 8;
        prep_kernel<<<(n + 255) / 256, 256>>>(x, xp, n);
        n = DIM * DIM / 8;
        prep_kernel<<<(n + 255) / 256, 256>>>(wq, wqp, n);
        prep_kernel<<<(n + 255) / 256, 256>>>(wo, wop, n);
        n = HKV * HD * DIM / 8;
        prep_kernel<<<(n + 255) / 256, 256>>>(wk, wkp, n);
        prep_kernel<<<(n + 255) / 256, 256>>>(wv, wvp, n);
    }

    // Fused QKV projections (mma.sync tf32, permuted operands)
    gemm_qkv_kernel<<<dim3(24, MTOT / 128), 256, GEMM_SMEM>>>(
        xp, wqp, wkp, wvp, qb, kb, vb);

    // RoPE on q and k
    {
        int tp_q = MTOT * HQ * (HD / 2);
        int tp_k = MTOT * HKV * (HD / 2);
        rope_kernel<<<(tp_q + 255) / 256, 256>>>(qb, freqs, HQ, tp_q);
        rope_kernel<<<(tp_k + 255) / 256, 256>>>(kb, freqs, HKV, tp_k);
    }

    // Attention (mma.sync tf32 flash) -> writes permuted tf32 output
    attn_mma_kernel<<<dim3(S_LEN / 128, HQ, BATCH), 256, ATTN_SMEM>>>(
        qb, kb, vb, aop);

    // Output projection (mma.sync tf32, permuted operands)
    gemm_tf32_kernel<<<dim3(DIM / 128, MTOT / 128), 256, GEMM_SMEM>>>(
        aop, wop, out, DIM, DIM);
}

// round 14
// speedup vs baseline: 6.5928x; 1.7296x over previous
#include <cuda_runtime.h>
#include <cuda_fp16.h>
#include <math_constants.h>
#include <cstdint>

#define BATCH 4
#define S_LEN 1024
#define DIM   2048
#define HQ    16
#define HKV   4
#define HD    128
#define MTOT  (BATCH * S_LEN)   // 4096

// Scratch (allocation-free rule: __device__ globals)
__device__ float  g_q[MTOT * HQ * HD];     // (4096, 2048) fp32 (rope in-place)
__device__ float  g_k[MTOT * HKV * HD];    // (4096, 512)  fp32
__device__ float  g_v[MTOT * HKV * HD];    // (4096, 512)  fp32
__device__ __half g_xh[MTOT * DIM];        // x, f16 + K-perm16
__device__ __half g_wqh[DIM * DIM];        // wq, f16 + K-perm16
__device__ __half g_wkh[HKV * HD * DIM];   // wk
__device__ __half g_wvh[HKV * HD * DIM];   // wv
__device__ __half g_woh[DIM * DIM];        // wo
__device__ __half g_aoh[MTOT * DIM];       // attn out, f16 + K-perm16

// ===========================================================================
// Helpers
// ===========================================================================
__device__ __forceinline__ void cp_async16(uint32_t dst, const void* src) {
    asm volatile("cp.async.cg.shared.global [%0], [%1], 16;\n"
                 :: "r"(dst), "l"(__cvta_generic_to_global(src)));
}
#define CP_COMMIT() asm volatile("cp.async.commit_group;\n" ::: "memory")
#define CP_WAIT0()  asm volatile("cp.async.wait_group 0;\n" ::: "memory")
#define CP_WAIT1()  asm volatile("cp.async.wait_group 1;\n" ::: "memory")

// D += A*B  (m16n8k16 f16, f32 accum)
__device__ __forceinline__ void mma_f16(float* c, const uint32_t* a,
                                        const uint32_t* b) {
    asm volatile(
        "mma.sync.aligned.m16n8k16.row.col.f32.f16.f16.f32 "
        "{%0,%1,%2,%3}, {%4,%5,%6,%7}, {%8,%9}, {%0,%1,%2,%3};"
        : "+f"(c[0]), "+f"(c[1]), "+f"(c[2]), "+f"(c[3])
        : "r"(a[0]), "r"(a[1]), "r"(a[2]), "r"(a[3]), "r"(b[0]), "r"(b[1]));
}

// Permute a group of 16 floats -> 16 halves:
// new = [0,1,8,9, 2,3,10,11, 4,5,12,13, 6,7,14,15]
// so lane tig's LDS.64 at 4*tig yields (k=2tig,2tig+1),(k=2tig+8,2tig+9).
__device__ __forceinline__ void perm16_store(__half* dst, float4 a, float4 b,
                                             float4 c, float4 d) {
    __half2 h[8];
    h[0] = __floats2half2_rn(a.x, a.y);
    h[1] = __floats2half2_rn(c.x, c.y);
    h[2] = __floats2half2_rn(a.z, a.w);
    h[3] = __floats2half2_rn(c.z, c.w);
    h[4] = __floats2half2_rn(b.x, b.y);
    h[5] = __floats2half2_rn(d.x, d.y);
    h[6] = __floats2half2_rn(b.z, b.w);
    h[7] = __floats2half2_rn(d.z, d.w);
    *(uint4*)dst       = *(uint4*)&h[0];
    *(uint4*)(dst + 8) = *(uint4*)&h[4];
}

// ===========================================================================
// Pre-pass: fp32 -> fp16 with K-perm16. One thread per 16 elements.
// ===========================================================================
__global__ void prep_kernel(const float* __restrict__ in, __half* __restrict__ out,
                            int n16) {
    int i = blockIdx.x * blockDim.x + threadIdx.x;
    if (i >= n16) return;
    const float4* p = (const float4*)(in + (size_t)i * 16);
    perm16_store(out + (size_t)i * 16, p[0], p[1], p[2], p[3]);
}

// ===========================================================================
// f16 mma.sync GEMM: C[M,N] = A[M,K] * B[N,K]^T, operands f16 K-perm16.
// CTA 128x128, BK=64 halves, 8 warps (64x32), double-buffered cp.async.
// Smem stride 80 halves -> fragment LDS.64 bank-conflict-free.
// ===========================================================================
#define SAH 80
#define TILE_HALVES (128 * SAH)                 // 10240 halves = 20480 B
#define GEMM_SMEM (4 * TILE_HALVES * 2)         // 81920 B

__device__ __forceinline__ void load_tile_pair(__half* smA, __half* smB,
                                               const __half* A, const __half* B,
                                               int K, int m0, int n0, int k0,
                                               int tid) {
    const int r  = tid >> 1;            // 0..127
    const int cb = (tid & 1) * 32;      // half col base (0 or 32)
    const __half* asrc = A + (size_t)(m0 + r) * K + k0 + cb;
    const __half* bsrc = B + (size_t)(n0 + r) * K + k0 + cb;
    uint32_t da = (uint32_t)__cvta_generic_to_shared(smA + r * SAH + cb);
    uint32_t db = (uint32_t)__cvta_generic_to_shared(smB + r * SAH + cb);
#pragma unroll
    for (int j = 0; j < 4; j++) {
        cp_async16(da + j * 16, asrc + j * 8);
        cp_async16(db + j * 16, bsrc + j * 8);
    }
}

__device__ __forceinline__ void gemm_core(__half* smem, const __half* A,
                                          const __half* B, float* C,
                                          int N, int K, int m0, int n0) {
    const int tid = threadIdx.x;
    const int wid = tid >> 5;
    const int lane = tid & 31;
    const int g   = lane >> 2;
    const int tig = lane & 3;
    const int wm = wid >> 2;
    const int wn = wid & 3;

    __half* A0 = smem;
    __half* A1 = smem + TILE_HALVES;
    __half* B0 = smem + 2 * TILE_HALVES;
    __half* B1 = smem + 3 * TILE_HALVES;

    float c[4][4][4];
#pragma unroll
    for (int i = 0; i < 4; i++)
#pragma unroll
        for (int j = 0; j < 4; j++)
#pragma unroll
            for (int q = 0; q < 4; q++) c[i][j][q] = 0.0f;

    const int NK = K >> 6;   // 32 for K=2048

    load_tile_pair(A0, B0, A, B, K, m0, n0, 0, tid);
    CP_COMMIT();

    for (int kt = 0; kt < NK; kt++) {
        if (kt + 1 < NK) {
            load_tile_pair((kt & 1) ? A0 : A1, (kt & 1) ? B0 : B1,
                           A, B, K, m0, n0, (kt + 1) * 64, tid);
            CP_COMMIT();
            CP_WAIT1();
        } else {
            CP_WAIT0();
        }
        __syncthreads();

        const __half* As = (kt & 1) ? A1 : A0;
        const __half* Bs = (kt & 1) ? B1 : B0;

#pragma unroll
        for (int kk = 0; kk < 4; kk++) {
            uint32_t af[4][4], bf[4][2];
#pragma unroll
            for (int ma = 0; ma < 4; ma++) {
                const __half* p = As + (wm * 64 + ma * 16 + g) * SAH + kk * 16 + 4 * tig;
                uint2 lo = *(const uint2*)p;
                uint2 hi = *(const uint2*)(p + 8 * SAH);
                af[ma][0] = lo.x; af[ma][2] = lo.y;
                af[ma][1] = hi.x; af[ma][3] = hi.y;
            }
#pragma unroll
            for (int nb = 0; nb < 4; nb++) {
                const __half* p = Bs + (wn * 32 + nb * 8 + g) * SAH + kk * 16 + 4 * tig;
                uint2 v = *(const uint2*)p;
                bf[nb][0] = v.x; bf[nb][1] = v.y;
            }
#pragma unroll
            for (int ma = 0; ma < 4; ma++)
#pragma unroll
                for (int nb = 0; nb < 4; nb++)
                    mma_f16(c[ma][nb], af[ma], bf[nb]);
        }
        __syncthreads();
    }

#pragma unroll
    for (int ma = 0; ma < 4; ma++) {
        const int r0 = m0 + wm * 64 + ma * 16 + g;
#pragma unroll
        for (int nb = 0; nb < 4; nb++) {
            const int col = n0 + wn * 32 + nb * 8 + 2 * tig;
            *(float2*)&C[(size_t)r0 * N + col] = make_float2(c[ma][nb][0], c[ma][nb][1]);
            *(float2*)&C[(size_t)(r0 + 8) * N + col] = make_float2(c[ma][nb][2], c[ma][nb][3]);
        }
    }
}

__global__ void __launch_bounds__(256, 2) gemm_qkv_kernel(
    const __half* __restrict__ x, const __half* __restrict__ wq,
    const __half* __restrict__ wk, const __half* __restrict__ wv,
    float* __restrict__ q, float* __restrict__ k, float* __restrict__ v) {
    extern __shared__ __half smh[];
    const int bx = blockIdx.x;
    const int m0 = blockIdx.y * 128;
    const __half* B; float* C; int N, n0;
    if (bx < 16)      { B = wq; C = q; N = 2048; n0 = bx * 128; }
    else if (bx < 20) { B = wk; C = k; N = 512;  n0 = (bx - 16) * 128; }
    else              { B = wv; C = v; N = 512;  n0 = (bx - 20) * 128; }
    gemm_core(smh, x, B, C, N, DIM, m0, n0);
}

__global__ void __launch_bounds__(256, 2) gemm_f16_kernel(
    const __half* __restrict__ A, const __half* __restrict__ B,
    float* __restrict__ C, int N, int K) {
    extern __shared__ __half smh[];
    gemm_core(smh, A, B, C, N, K, blockIdx.y * 128, blockIdx.x * 128);
}

// ---------------------------------------------------------------------------
// RoPE (Llama-style adjacent pairs): in-place on (MTOT, nheads*HD)
// ---------------------------------------------------------------------------
__global__ void rope_kernel(float* __restrict__ t, const float* __restrict__ freqs,
                            int nheads, int total_pairs) {
    int idx = blockIdx.x * blockDim.x + threadIdx.x;
    if (idx >= total_pairs) return;
    int p = idx & (HD / 2 - 1);
    int h = (idx >> 6) % nheads;
    int m = idx / ((HD / 2) * nheads);
    int s = m & (S_LEN - 1);
    float ang = freqs[s * (HD / 2) + p];
    float c = cosf(ang), sn = sinf(ang);
    float* base = t + (size_t)m * nheads * HD + h * HD + 2 * p;
    float x0 = base[0], x1 = base[1];
    base[0] = x0 * c - x1 * sn;
    base[1] = x0 * sn + x1 * c;
}

// ===========================================================================
// Tensorized flash attention (mma.sync f16, fp32 softmax), causal, GQA.
// CTA = 128 q-rows of one (b, qh). 8 warps x 16-row m-blocks. KV tile 64.
// smem (halves): Qs[128][144], Ks[64][144], VsT[128][82], Ps[8][16][80]
// VTH=82 (41 words, odd) keeps the transpose STORES conflict-free; fragment
// READS from VsT use 2x LDS.32 because odd-row uint2 would be misaligned.
// Output written f16 + K-perm16 straight into g_aoh.
// ===========================================================================
#define QSH 144
#define VTH 82
#define PSH 80
#define ATTN_SMEM ((128 * QSH + 64 * QSH + 128 * VTH + 8 * 16 * PSH) * 2)  // 96768 B

__global__ void __launch_bounds__(256, 1) attn_mma_kernel(
    const float* __restrict__ q, const float* __restrict__ k,
    const float* __restrict__ v, __half* __restrict__ o) {
    extern __shared__ __half smh[];
    __half* Qs  = smh;                   // 128*144
    __half* Ks  = Qs + 128 * QSH;        // 64*144
    __half* VsT = Ks + 64 * QSH;         // 128*82  [d][t-perm16]
    __half* Ps  = VsT + 128 * VTH;       // per-warp 16*80

    const int tid  = threadIdx.x;
    const int lane = tid & 31;
    const int wid  = tid >> 5;
    const int g    = lane >> 2;
    const int tig  = lane & 3;
    const int qt = blockIdx.x;
    const int qh = blockIdx.y;
    const int b  = blockIdx.z;
    const int kh = qh >> 2;
    const int q0 = qt * 128;
    const int wm0 = wid * 16;

    const float scale = 0.08838834764831845f;  // 1/sqrt(128)

    // ---- Load Q tile (f16, K-perm16): 128 rows x 8 groups of 16 ----
    const float* qp = q + ((size_t)(b * S_LEN + q0)) * (HQ * HD) + qh * HD;
#pragma unroll
    for (int it = 0; it < 4; it++) {
        int gid = it * 256 + tid;
        int row = gid >> 3, gi = gid & 7;
        const float4* p = (const float4*)(qp + (size_t)row * (HQ * HD) + gi * 16);
        perm16_store(&Qs[row * QSH + gi * 16], p[0], p[1], p[2], p[3]);
    }

    float oacc[16][4];
#pragma unroll
    for (int nf = 0; nf < 16; nf++)
#pragma unroll
        for (int j = 0; j < 4; j++) oacc[nf][j] = 0.0f;
    float mi[2] = {-CUDART_INF_F, -CUDART_INF_F};
    float li[2] = {0.0f, 0.0f};

    const int nkt = 2 * qt + 2;
    for (int kt = 0; kt < nkt; kt++) {
        const int t0 = kt * 64;
        __syncthreads();

        // ---- K tile (64 rows x 8 groups, f16 perm16) ----
        const float* kp = k + ((size_t)(b * S_LEN + t0)) * (HKV * HD) + kh * HD;
#pragma unroll
        for (int it = 0; it < 2; it++) {
            int gid = it * 256 + tid;
            int row = gid >> 3, gi = gid & 7;
            const float4* p = (const float4*)(kp + (size_t)row * (HKV * HD) + gi * 16);
            perm16_store(&Ks[row * QSH + gi * 16], p[0], p[1], p[2], p[3]);
        }
        // ---- V tile transposed + t-perm16: VsT[d][perm(t)] ----
        const float* vp = v + ((size_t)(b * S_LEN + t0)) * (HKV * HD) + kh * HD;
#pragma unroll
        for (int it = 0; it < 8; it++) {
            int idx = it * 256 + tid;          // 2048 quads
            int d = idx & 127;
            int s = idx >> 7;                  // 0..15
            int gi = s >> 2, si = s & 3;
            int tb = 16 * gi;
            float a0 = vp[(size_t)(tb + 2 * si)     * (HKV * HD) + d];
            float a1 = vp[(size_t)(tb + 2 * si + 1) * (HKV * HD) + d];
            float a2 = vp[(size_t)(tb + 2 * si + 8) * (HKV * HD) + d];
            float a3 = vp[(size_t)(tb + 2 * si + 9) * (HKV * HD) + d];
            __half2 h01 = __floats2half2_rn(a0, a1);
            __half2 h23 = __floats2half2_rn(a2, a3);
            __half2* dst = (__half2*)&VsT[d * VTH + tb + 4 * si];
            dst[0] = h01; dst[1] = h23;
        }
        __syncthreads();

        if (t0 > q0 + wm0 + 15) continue;

        // ---- S = Q K^T (16 x 64 per warp), k = d = 128 -> 8 kk steps ----
        float s[8][4];
#pragma unroll
        for (int nb = 0; nb < 8; nb++)
#pragma unroll
            for (int j = 0; j < 4; j++) s[nb][j] = 0.0f;

#pragma unroll
        for (int kk = 0; kk < 8; kk++) {
            const __half* ap = Qs + (wm0 + g) * QSH + kk * 16 + 4 * tig;
            uint2 lo = *(const uint2*)ap;
            uint2 hi = *(const uint2*)(ap + 8 * QSH);
            uint32_t af[4] = {lo.x, hi.x, lo.y, hi.y};
#pragma unroll
            for (int nb = 0; nb < 8; nb++) {
                const __half* bp = Ks + (nb * 8 + g) * QSH + kk * 16 + 4 * tig;
                uint2 v2 = *(const uint2*)bp;
                uint32_t bf[2] = {v2.x, v2.y};
                mma_f16(s[nb], af, bf);
            }
        }

        // ---- Scale + causal mask ----
        const int row0 = q0 + wm0 + g;
#pragma unroll
        for (int nb = 0; nb < 8; nb++) {
#pragma unroll
            for (int j = 0; j < 4; j++) {
                int col = t0 + nb * 8 + 2 * tig + (j & 1);
                int row = row0 + ((j >= 2) ? 8 : 0);
                float sc = s[nb][j] * scale;
                s[nb][j] = (col > row) ? -1e9f : sc;
            }
        }

        // ---- Online softmax (rows g, g+8 per lane) ----
#pragma unroll
        for (int h = 0; h < 2; h++) {
            float mx = -CUDART_INF_F;
#pragma unroll
            for (int nb = 0; nb < 8; nb++)
                mx = fmaxf(mx, fmaxf(s[nb][2 * h], s[nb][2 * h + 1]));
            mx = fmaxf(mx, __shfl_xor_sync(0xffffffffu, mx, 1));
            mx = fmaxf(mx, __shfl_xor_sync(0xffffffffu, mx, 2));
            float mnew = fmaxf(mi[h], mx);
            float al = __expf(mi[h] - mnew);
            float rs = 0.0f;
#pragma unroll
            for (int nb = 0; nb < 8; nb++) {
                float p0 = __expf(s[nb][2 * h] - mnew);
                float p1 = __expf(s[nb][2 * h + 1] - mnew);
                s[nb][2 * h] = p0;
                s[nb][2 * h + 1] = p1;
                rs += p0 + p1;
            }
            rs += __shfl_xor_sync(0xffffffffu, rs, 1);
            rs += __shfl_xor_sync(0xffffffffu, rs, 2);
            li[h] = li[h] * al + rs;
            mi[h] = mnew;
#pragma unroll
            for (int nf = 0; nf < 16; nf++) {
                oacc[nf][2 * h]     *= al;
                oacc[nf][2 * h + 1] *= al;
            }
        }

        // ---- Store P (f16, t-perm16) to per-warp smem ----
        // old pair (cols nb*8+2tig, +1) -> col 16*(nb>>1) + 4*tig + 2*(nb&1)
        __half* Pw = Ps + wid * 16 * PSH;
#pragma unroll
        for (int nb = 0; nb < 8; nb++) {
            int off = 16 * (nb >> 1) + 4 * tig + 2 * (nb & 1);
            *(__half2*)&Pw[g * PSH + off] = __floats2half2_rn(s[nb][0], s[nb][1]);
            *(__half2*)&Pw[(g + 8) * PSH + off] = __floats2half2_rn(s[nb][2], s[nb][3]);
        }
        __syncwarp();

        // ---- O += P V  (16 x 128 per warp), k = t = 64 -> 4 kk steps ----
#pragma unroll
        for (int kk = 0; kk < 4; kk++) {
            const __half* ap = Pw + g * PSH + kk * 16 + 4 * tig;
            uint2 lo = *(const uint2*)ap;
            uint2 hi = *(const uint2*)(ap + 8 * PSH);
            uint32_t af[4] = {lo.x, hi.x, lo.y, hi.y};
#pragma unroll
            for (int nf = 0; nf < 16; nf++) {
                // VTH=82: odd word row stride -> uint2 would be misaligned for
                // odd rows; use two 4-byte loads (even half offsets, aligned).
                const __half* bp = VsT + (nf * 8 + g) * VTH + kk * 16 + 4 * tig;
                uint32_t bf[2];
                bf[0] = *(const uint32_t*)bp;
                bf[1] = *(const uint32_t*)(bp + 2);
                mma_f16(oacc[nf], af, bf);
            }
        }
        __syncwarp();
    }

    // ---- Normalize + store f16 K-perm16 (A operand of wo GEMM) ----
    const float inv0 = 1.0f / li[0];
    const float inv1 = 1.0f / li[1];
    __half* ob = o + ((size_t)(b * S_LEN + q0 + wm0 + g)) * (HQ * HD) + qh * HD;
#pragma unroll
    for (int nf = 0; nf < 16; nf++) {
        int off = 16 * (nf >> 1) + 4 * tig + 2 * (nf & 1);
        *(__half2*)&ob[off] = __floats2half2_rn(oacc[nf][0] * inv0, oacc[nf][1] * inv0);
        *(__half2*)&ob[(size_t)8 * (HQ * HD) + off] =
            __floats2half2_rn(oacc[nf][2] * inv1, oacc[nf][3] * inv1);
    }
}

// ---------------------------------------------------------------------------
// Launch
// ---------------------------------------------------------------------------
extern "C" void kernel_launch(void* const* d_in, const int* in_sizes, int n_in,
                              void* d_out, int out_size) {
    const float* x     = (const float*)d_in[0];
    const float* freqs = (const float*)d_in[2];
    const float* wq    = (const float*)d_in[4];
    const float* wk    = (const float*)d_in[5];
    const float* wv    = (const float*)d_in[6];
    const float* wo    = (const float*)d_in[7];
    float* out = (float*)d_out;

    float *qb, *kb, *vb;
    __half *xh, *wqh, *wkh, *wvh, *woh, *aoh;
    cudaGetSymbolAddress((void**)&qb,  g_q);
    cudaGetSymbolAddress((void**)&kb,  g_k);
    cudaGetSymbolAddress((void**)&vb,  g_v);
    cudaGetSymbolAddress((void**)&xh,  g_xh);
    cudaGetSymbolAddress((void**)&wqh, g_wqh);
    cudaGetSymbolAddress((void**)&wkh, g_wkh);
    cudaGetSymbolAddress((void**)&wvh, g_wvh);
    cudaGetSymbolAddress((void**)&woh, g_woh);
    cudaGetSymbolAddress((void**)&aoh, g_aoh);

    static bool attr_done = false;
    if (!attr_done) {
        cudaFuncSetAttribute(gemm_qkv_kernel,
                             cudaFuncAttributeMaxDynamicSharedMemorySize, GEMM_SMEM);
        cudaFuncSetAttribute(gemm_f16_kernel,
                             cudaFuncAttributeMaxDynamicSharedMemorySize, GEMM_SMEM);
        cudaFuncSetAttribute(attn_mma_kernel,
                             cudaFuncAttributeMaxDynamicSharedMemorySize, ATTN_SMEM);
        attr_done = true;
    }

    // Pre-pass: f16 convert + K-perm16 all GEMM operands
    {
        int n;
        n = MTOT * DIM / 16;
        prep_kernel<<<(n + 255) / 256, 256>>>(x, xh, n);
        n = DIM * DIM / 16;
        prep_kernel<<<(n + 255) / 256, 256>>>(wq, wqh, n);
        prep_kernel<<<(n + 255) / 256, 256>>>(wo, woh, n);
        n = HKV * HD * DIM / 16;
        prep_kernel<<<(n + 255) / 256, 256>>>(wk, wkh, n);
        prep_kernel<<<(n + 255) / 256, 256>>>(wv, wvh, n);
    }

    // Fused QKV projections (mma.sync f16)
    gemm_qkv_kernel<<<dim3(24, MTOT / 128), 256, GEMM_SMEM>>>(
        xh, wqh, wkh, wvh, qb, kb, vb);

    // RoPE on q and k (fp32)
    {
        int tp_q = MTOT * HQ * (HD / 2);
        int tp_k = MTOT * HKV * (HD / 2);
        rope_kernel<<<(tp_q + 255) / 256, 256>>>(qb, freqs, HQ, tp_q);
        rope_kernel<<<(tp_k + 255) / 256, 256>>>(kb, freqs, HKV, tp_k);
    }

    // Attention (mma.sync f16 flash) -> writes f16 perm16 output
    attn_mma_kernel<<<dim3(S_LEN / 128, HQ, BATCH), 256, ATTN_SMEM>>>(
        qb, kb, vb, aoh);

    // Output projection (mma.sync f16)
    gemm_f16_kernel<<<dim3(DIM / 128, MTOT / 128), 256, GEMM_SMEM>>>(
        aoh, woh, out, DIM, DIM);
}

// round 15
// speedup vs baseline: 6.9105x; 1.0482x over previous
#include <cuda_runtime.h>
#include <cuda_fp16.h>
#include <math_constants.h>
#include <cstdint>

#define BATCH 4
#define S_LEN 1024
#define DIM   2048
#define HQ    16
#define HKV   4
#define HD    128
#define MTOT  (BATCH * S_LEN)   // 4096

// Scratch (allocation-free rule: __device__ globals)
__device__ __half g_qh[MTOT * HQ * HD];    // q, f16 + d-perm16, rope applied
__device__ __half g_kh[MTOT * HKV * HD];   // k, f16 + d-perm16, rope applied
__device__ __half g_vh[MTOT * HKV * HD];   // v, f16 plain
__device__ __half g_xh[MTOT * DIM];        // x, f16 + K-perm16
__device__ __half g_wqh[DIM * DIM];        // wq, f16 + K-perm16
__device__ __half g_wkh[HKV * HD * DIM];   // wk
__device__ __half g_wvh[HKV * HD * DIM];   // wv
__device__ __half g_woh[DIM * DIM];        // wo
__device__ __half g_aoh[MTOT * DIM];       // attn out, f16 + K-perm16
__device__ float  g_ct[S_LEN * HD / 2];    // cos(freqs)
__device__ float  g_st[S_LEN * HD / 2];    // sin(freqs)

// ===========================================================================
// Helpers
// ===========================================================================
__device__ __forceinline__ void cp_async16(uint32_t dst, const void* src) {
    asm volatile("cp.async.cg.shared.global [%0], [%1], 16;\n"
                 :: "r"(dst), "l"(__cvta_generic_to_global(src)));
}
#define CP_COMMIT() asm volatile("cp.async.commit_group;\n" ::: "memory")
#define CP_WAIT0()  asm volatile("cp.async.wait_group 0;\n" ::: "memory")
#define CP_WAIT1()  asm volatile("cp.async.wait_group 1;\n" ::: "memory")

// D += A*B  (m16n8k16 f16, f32 accum)
__device__ __forceinline__ void mma_f16(float* c, const uint32_t* a,
                                        const uint32_t* b) {
    asm volatile(
        "mma.sync.aligned.m16n8k16.row.col.f32.f16.f16.f32 "
        "{%0,%1,%2,%3}, {%4,%5,%6,%7}, {%8,%9}, {%0,%1,%2,%3};"
        : "+f"(c[0]), "+f"(c[1]), "+f"(c[2]), "+f"(c[3])
        : "r"(a[0]), "r"(a[1]), "r"(a[2]), "r"(a[3]), "r"(b[0]), "r"(b[1]));
}

// Permute a group of 16 floats -> 16 halves:
// new = [0,1,8,9, 2,3,10,11, 4,5,12,13, 6,7,14,15]
__device__ __forceinline__ void perm16_store(__half* dst, float4 a, float4 b,
                                             float4 c, float4 d) {
    __half2 h[8];
    h[0] = __floats2half2_rn(a.x, a.y);
    h[1] = __floats2half2_rn(c.x, c.y);
    h[2] = __floats2half2_rn(a.z, a.w);
    h[3] = __floats2half2_rn(c.z, c.w);
    h[4] = __floats2half2_rn(b.x, b.y);
    h[5] = __floats2half2_rn(d.x, d.y);
    h[6] = __floats2half2_rn(b.z, b.w);
    h[7] = __floats2half2_rn(d.z, d.w);
    *(uint4*)dst       = *(uint4*)&h[0];
    *(uint4*)(dst + 8) = *(uint4*)&h[4];
}

// ===========================================================================
// Pre-pass kernels
// ===========================================================================
__global__ void prep_kernel(const float* __restrict__ in, __half* __restrict__ out,
                            int n16) {
    int i = blockIdx.x * blockDim.x + threadIdx.x;
    if (i >= n16) return;
    const float4* p = (const float4*)(in + (size_t)i * 16);
    perm16_store(out + (size_t)i * 16, p[0], p[1], p[2], p[3]);
}

__global__ void cs_kernel(const float* __restrict__ freqs) {
    int i = blockIdx.x * blockDim.x + threadIdx.x;
    if (i >= S_LEN * (HD / 2)) return;
    float a = freqs[i];
    g_ct[i] = cosf(a);
    g_st[i] = sinf(a);
}

// ===========================================================================
// f16 mma.sync GEMM: C[M,N] = A[M,K] * B[N,K]^T, operands f16 K-perm16.
// CTA 128x128, BK=64 halves, 8 warps (64x32), double-buffered cp.async.
// Epilogue modes: 1 = rope+perm16 -> f16 (q/k), 2 = plain -> f16 (v),
//                 3 = plain -> f32 (final output).
// ===========================================================================
#define SAH 80
#define TILE_HALVES (128 * SAH)                 // 10240 halves = 20480 B
#define GEMM_SMEM (4 * TILE_HALVES * 2)         // 81920 B

__device__ __forceinline__ void load_tile_pair(__half* smA, __half* smB,
                                               const __half* A, const __half* B,
                                               int K, int m0, int n0, int k0,
                                               int tid) {
    const int r  = tid >> 1;            // 0..127
    const int cb = (tid & 1) * 32;      // half col base (0 or 32)
    const __half* asrc = A + (size_t)(m0 + r) * K + k0 + cb;
    const __half* bsrc = B + (size_t)(n0 + r) * K + k0 + cb;
    uint32_t da = (uint32_t)__cvta_generic_to_shared(smA + r * SAH + cb);
    uint32_t db = (uint32_t)__cvta_generic_to_shared(smB + r * SAH + cb);
#pragma unroll
    for (int j = 0; j < 4; j++) {
        cp_async16(da + j * 16, asrc + j * 8);
        cp_async16(db + j * 16, bsrc + j * 8);
    }
}

template <int EPI>
__device__ __forceinline__ void gemm_core(__half* smem, const __half* A,
                                          const __half* B, void* Cout,
                                          int N, int K, int m0, int n0) {
    const int tid = threadIdx.x;
    const int wid = tid >> 5;
    const int lane = tid & 31;
    const int g   = lane >> 2;
    const int tig = lane & 3;
    const int wm = wid >> 2;
    const int wn = wid & 3;

    __half* A0 = smem;
    __half* A1 = smem + TILE_HALVES;
    __half* B0 = smem + 2 * TILE_HALVES;
    __half* B1 = smem + 3 * TILE_HALVES;

    float c[4][4][4];
#pragma unroll
    for (int i = 0; i < 4; i++)
#pragma unroll
        for (int j = 0; j < 4; j++)
#pragma unroll
            for (int q = 0; q < 4; q++) c[i][j][q] = 0.0f;

    const int NK = K >> 6;   // 32 for K=2048

    load_tile_pair(A0, B0, A, B, K, m0, n0, 0, tid);
    CP_COMMIT();

    for (int kt = 0; kt < NK; kt++) {
        if (kt + 1 < NK) {
            load_tile_pair((kt & 1) ? A0 : A1, (kt & 1) ? B0 : B1,
                           A, B, K, m0, n0, (kt + 1) * 64, tid);
            CP_COMMIT();
            CP_WAIT1();
        } else {
            CP_WAIT0();
        }
        __syncthreads();

        const __half* As = (kt & 1) ? A1 : A0;
        const __half* Bs = (kt & 1) ? B1 : B0;

#pragma unroll
        for (int kk = 0; kk < 4; kk++) {
            uint32_t af[4][4], bf[4][2];
#pragma unroll
            for (int ma = 0; ma < 4; ma++) {
                const __half* p = As + (wm * 64 + ma * 16 + g) * SAH + kk * 16 + 4 * tig;
                uint2 lo = *(const uint2*)p;
                uint2 hi = *(const uint2*)(p + 8 * SAH);
                af[ma][0] = lo.x; af[ma][2] = lo.y;
                af[ma][1] = hi.x; af[ma][3] = hi.y;
            }
#pragma unroll
            for (int nb = 0; nb < 4; nb++) {
                const __half* p = Bs + (wn * 32 + nb * 8 + g) * SAH + kk * 16 + 4 * tig;
                uint2 v = *(const uint2*)p;
                bf[nb][0] = v.x; bf[nb][1] = v.y;
            }
#pragma unroll
            for (int ma = 0; ma < 4; ma++)
#pragma unroll
                for (int nb = 0; nb < 4; nb++)
                    mma_f16(c[ma][nb], af[ma], bf[nb]);
        }
        __syncthreads();
    }

#pragma unroll
    for (int ma = 0; ma < 4; ma++) {
        const int r0 = m0 + wm * 64 + ma * 16 + g;
#pragma unroll
        for (int nb = 0; nb < 4; nb++) {
            const int col = n0 + wn * 32 + nb * 8 + 2 * tig;
            float* cc = c[ma][nb];
            if (EPI == 3) {
                float* C = (float*)Cout;
                *(float2*)&C[(size_t)r0 * N + col] = make_float2(cc[0], cc[1]);
                *(float2*)&C[(size_t)(r0 + 8) * N + col] = make_float2(cc[2], cc[3]);
            } else if (EPI == 2) {
                __half* C = (__half*)Cout;
                *(__half2*)&C[(size_t)r0 * N + col] = __floats2half2_rn(cc[0], cc[1]);
                *(__half2*)&C[(size_t)(r0 + 8) * N + col] = __floats2half2_rn(cc[2], cc[3]);
            } else {
                // rope (fp32) + perm16 + f16 store
                __half* C = (__half*)Cout;
                const int p = (col & 127) >> 1;           // rope pair index
                const int j = (col & 15) >> 1;
                const int off = (col & ~15) + ((j < 4) ? 4 * j : 4 * j - 14);
                const int s0 = r0 & (S_LEN - 1);          // token position
                float c0 = g_ct[s0 * 64 + p],       sn0 = g_st[s0 * 64 + p];
                float c1 = g_ct[(s0 + 8) * 64 + p], sn1 = g_st[(s0 + 8) * 64 + p];
                *(__half2*)&C[(size_t)r0 * N + off] =
                    __floats2half2_rn(cc[0] * c0 - cc[1] * sn0,
                                      cc[0] * sn0 + cc[1] * c0);
                *(__half2*)&C[(size_t)(r0 + 8) * N + off] =
                    __floats2half2_rn(cc[2] * c1 - cc[3] * sn1,
                                      cc[2] * sn1 + cc[3] * c1);
            }
        }
    }
}

// Fused QKV + RoPE: grid.x = 16 (wq) + 4 (wk) + 4 (wv), grid.y = 32 m-tiles.
__global__ void __launch_bounds__(256, 2) gemm_qkv_kernel(
    const __half* __restrict__ x, const __half* __restrict__ wq,
    const __half* __restrict__ wk, const __half* __restrict__ wv,
    __half* __restrict__ q, __half* __restrict__ k, __half* __restrict__ v) {
    extern __shared__ __half smh[];
    const int bx = blockIdx.x;
    const int m0 = blockIdx.y * 128;
    if (bx < 16) {
        gemm_core<1>(smh, x, wq, q, 2048, DIM, m0, bx * 128);
    } else if (bx < 20) {
        gemm_core<1>(smh, x, wk, k, 512, DIM, m0, (bx - 16) * 128);
    } else {
        gemm_core<2>(smh, x, wv, v, 512, DIM, m0, (bx - 20) * 128);
    }
}

__global__ void __launch_bounds__(256, 2) gemm_out_kernel(
    const __half* __restrict__ A, const __half* __restrict__ B,
    float* __restrict__ C, int N, int K) {
    extern __shared__ __half smh[];
    gemm_core<3>(smh, A, B, C, N, K, blockIdx.y * 128, blockIdx.x * 128);
}

// ===========================================================================
// Tensorized flash attention (mma.sync f16, fp32 softmax), causal, GQA.
// CTA = 128 q-rows of one (b, qh). 8 warps x 16-row m-blocks. KV tile 64.
// Inputs already f16: q/k d-perm16 (rope applied), v plain [t][d].
// smem (halves): Qs[128][144], Ks[64][144], VsT[128][82], Ps[8][16][80]
// Output written f16 + K-perm16 straight into g_aoh.
// ===========================================================================
#define QSH 144
#define VTH 82
#define PSH 80
#define ATTN_SMEM ((128 * QSH + 64 * QSH + 128 * VTH + 8 * 16 * PSH) * 2)  // 96768 B

__global__ void __launch_bounds__(256, 1) attn_mma_kernel(
    const __half* __restrict__ q, const __half* __restrict__ k,
    const __half* __restrict__ v, __half* __restrict__ o) {
    extern __shared__ __half smh[];
    __half* Qs  = smh;                   // 128*144
    __half* Ks  = Qs + 128 * QSH;        // 64*144
    __half* VsT = Ks + 64 * QSH;         // 128*82  [d][t-perm16]
    __half* Ps  = VsT + 128 * VTH;       // per-warp 16*80

    const int tid  = threadIdx.x;
    const int lane = tid & 31;
    const int wid  = tid >> 5;
    const int g    = lane >> 2;
    const int tig  = lane & 3;
    const int qt = blockIdx.x;
    const int qh = blockIdx.y;
    const int b  = blockIdx.z;
    const int kh = qh >> 2;
    const int q0 = qt * 128;
    const int wm0 = wid * 16;

    const float scale = 0.08838834764831845f;  // 1/sqrt(128)

    // ---- Load Q tile (already f16 perm16): plain copy ----
    const __half* qp = q + ((size_t)(b * S_LEN + q0)) * (HQ * HD) + qh * HD;
#pragma unroll
    for (int it = 0; it < 4; it++) {
        int gid = it * 256 + tid;
        int row = gid >> 3, gi = gid & 7;
        const uint4* p = (const uint4*)(qp + (size_t)row * (HQ * HD) + gi * 16);
        *(uint4*)&Qs[row * QSH + gi * 16]     = p[0];
        *(uint4*)&Qs[row * QSH + gi * 16 + 8] = p[1];
    }

    float oacc[16][4];
#pragma unroll
    for (int nf = 0; nf < 16; nf++)
#pragma unroll
        for (int j = 0; j < 4; j++) oacc[nf][j] = 0.0f;
    float mi[2] = {-CUDART_INF_F, -CUDART_INF_F};
    float li[2] = {0.0f, 0.0f};

    const int nkt = 2 * qt + 2;
    for (int kt = 0; kt < nkt; kt++) {
        const int t0 = kt * 64;
        __syncthreads();

        // ---- K tile (f16 perm16): plain copy ----
        const __half* kp = k + ((size_t)(b * S_LEN + t0)) * (HKV * HD) + kh * HD;
#pragma unroll
        for (int it = 0; it < 2; it++) {
            int gid = it * 256 + tid;
            int row = gid >> 3, gi = gid & 7;
            const uint4* p = (const uint4*)(kp + (size_t)row * (HKV * HD) + gi * 16);
            *(uint4*)&Ks[row * QSH + gi * 16]     = p[0];
            *(uint4*)&Ks[row * QSH + gi * 16 + 8] = p[1];
        }
        // ---- V tile transposed + t-perm16: VsT[d][perm(t)] ----
        const __half* vp = v + ((size_t)(b * S_LEN + t0)) * (HKV * HD) + kh * HD;
#pragma unroll
        for (int it = 0; it < 8; it++) {
            int idx = it * 256 + tid;          // 2048 quads
            int d = idx & 127;
            int s = idx >> 7;                  // 0..15
            int gi = s >> 2, si = s & 3;
            int tb = 16 * gi;
            __half a0 = vp[(size_t)(tb + 2 * si)     * (HKV * HD) + d];
            __half a1 = vp[(size_t)(tb + 2 * si + 1) * (HKV * HD) + d];
            __half a2 = vp[(size_t)(tb + 2 * si + 8) * (HKV * HD) + d];
            __half a3 = vp[(size_t)(tb + 2 * si + 9) * (HKV * HD) + d];
            __half2* dst = (__half2*)&VsT[d * VTH + tb + 4 * si];
            dst[0] = __halves2half2(a0, a1);
            dst[1] = __halves2half2(a2, a3);
        }
        __syncthreads();

        if (t0 > q0 + wm0 + 15) continue;

        // ---- S = Q K^T (16 x 64 per warp), k = d = 128 -> 8 kk steps ----
        float s[8][4];
#pragma unroll
        for (int nb = 0; nb < 8; nb++)
#pragma unroll
            for (int j = 0; j < 4; j++) s[nb][j] = 0.0f;

#pragma unroll
        for (int kk = 0; kk < 8; kk++) {
            const __half* ap = Qs + (wm0 + g) * QSH + kk * 16 + 4 * tig;
            uint2 lo = *(const uint2*)ap;
            uint2 hi = *(const uint2*)(ap + 8 * QSH);
            uint32_t af[4] = {lo.x, hi.x, lo.y, hi.y};
#pragma unroll
            for (int nb = 0; nb < 8; nb++) {
                const __half* bp = Ks + (nb * 8 + g) * QSH + kk * 16 + 4 * tig;
                uint2 v2 = *(const uint2*)bp;
                uint32_t bf[2] = {v2.x, v2.y};
                mma_f16(s[nb], af, bf);
            }
        }

        // ---- Scale + causal mask ----
        const int row0 = q0 + wm0 + g;
#pragma unroll
        for (int nb = 0; nb < 8; nb++) {
#pragma unroll
            for (int j = 0; j < 4; j++) {
                int col = t0 + nb * 8 + 2 * tig + (j & 1);
                int row = row0 + ((j >= 2) ? 8 : 0);
                float sc = s[nb][j] * scale;
                s[nb][j] = (col > row) ? -1e9f : sc;
            }
        }

        // ---- Online softmax (rows g, g+8 per lane) ----
#pragma unroll
        for (int h = 0; h < 2; h++) {
            float mx = -CUDART_INF_F;
#pragma unroll
            for (int nb = 0; nb < 8; nb++)
                mx = fmaxf(mx, fmaxf(s[nb][2 * h], s[nb][2 * h + 1]));
            mx = fmaxf(mx, __shfl_xor_sync(0xffffffffu, mx, 1));
            mx = fmaxf(mx, __shfl_xor_sync(0xffffffffu, mx, 2));
            float mnew = fmaxf(mi[h], mx);
            float al = __expf(mi[h] - mnew);
            float rs = 0.0f;
#pragma unroll
            for (int nb = 0; nb < 8; nb++) {
                float p0 = __expf(s[nb][2 * h] - mnew);
                float p1 = __expf(s[nb][2 * h + 1] - mnew);
                s[nb][2 * h] = p0;
                s[nb][2 * h + 1] = p1;
                rs += p0 + p1;
            }
            rs += __shfl_xor_sync(0xffffffffu, rs, 1);
            rs += __shfl_xor_sync(0xffffffffu, rs, 2);
            li[h] = li[h] * al + rs;
            mi[h] = mnew;
#pragma unroll
            for (int nf = 0; nf < 16; nf++) {
                oacc[nf][2 * h]     *= al;
                oacc[nf][2 * h + 1] *= al;
            }
        }

        // ---- Store P (f16, t-perm16) to per-warp smem ----
        __half* Pw = Ps + wid * 16 * PSH;
#pragma unroll
        for (int nb = 0; nb < 8; nb++) {
            int off = 16 * (nb >> 1) + 4 * tig + 2 * (nb & 1);
            *(__half2*)&Pw[g * PSH + off] = __floats2half2_rn(s[nb][0], s[nb][1]);
            *(__half2*)&Pw[(g + 8) * PSH + off] = __floats2half2_rn(s[nb][2], s[nb][3]);
        }
        __syncwarp();

        // ---- O += P V  (16 x 128 per warp), k = t = 64 -> 4 kk steps ----
#pragma unroll
        for (int kk = 0; kk < 4; kk++) {
            const __half* ap = Pw + g * PSH + kk * 16 + 4 * tig;
            uint2 lo = *(const uint2*)ap;
            uint2 hi = *(const uint2*)(ap + 8 * PSH);
            uint32_t af[4] = {lo.x, hi.x, lo.y, hi.y};
#pragma unroll
            for (int nf = 0; nf < 16; nf++) {
                // VTH=82 (odd word stride): use two aligned 4-byte loads.
                const __half* bp = VsT + (nf * 8 + g) * VTH + kk * 16 + 4 * tig;
                uint32_t bf[2];
                bf[0] = *(const uint32_t*)bp;
                bf[1] = *(const uint32_t*)(bp + 2);
                mma_f16(oacc[nf], af, bf);
            }
        }
        __syncwarp();
    }

    // ---- Normalize + store f16 K-perm16 (A operand of wo GEMM) ----
    const float inv0 = 1.0f / li[0];
    const float inv1 = 1.0f / li[1];
    __half* ob = o + ((size_t)(b * S_LEN + q0 + wm0 + g)) * (HQ * HD) + qh * HD;
#pragma unroll
    for (int nf = 0; nf < 16; nf++) {
        int off = 16 * (nf >> 1) + 4 * tig + 2 * (nf & 1);
        *(__half2*)&ob[off] = __floats2half2_rn(oacc[nf][0] * inv0, oacc[nf][1] * inv0);
        *(__half2*)&ob[(size_t)8 * (HQ * HD) + off] =
            __floats2half2_rn(oacc[nf][2] * inv1, oacc[nf][3] * inv1);
    }
}

// ---------------------------------------------------------------------------
// Launch
// ---------------------------------------------------------------------------
extern "C" void kernel_launch(void* const* d_in, const int* in_sizes, int n_in,
                              void* d_out, int out_size) {
    const float* x     = (const float*)d_in[0];
    const float* freqs = (const float*)d_in[2];
    const float* wq    = (const float*)d_in[4];
    const float* wk    = (const float*)d_in[5];
    const float* wv    = (const float*)d_in[6];
    const float* wo    = (const float*)d_in[7];
    float* out = (float*)d_out;

    __half *qh, *kh, *vh, *xh, *wqh, *wkh, *wvh, *woh, *aoh;
    cudaGetSymbolAddress((void**)&qh,  g_qh);
    cudaGetSymbolAddress((void**)&kh,  g_kh);
    cudaGetSymbolAddress((void**)&vh,  g_vh);
    cudaGetSymbolAddress((void**)&xh,  g_xh);
    cudaGetSymbolAddress((void**)&wqh, g_wqh);
    cudaGetSymbolAddress((void**)&wkh, g_wkh);
    cudaGetSymbolAddress((void**)&wvh, g_wvh);
    cudaGetSymbolAddress((void**)&woh, g_woh);
    cudaGetSymbolAddress((void**)&aoh, g_aoh);

    static bool attr_done = false;
    if (!attr_done) {
        cudaFuncSetAttribute(gemm_qkv_kernel,
                             cudaFuncAttributeMaxDynamicSharedMemorySize, GEMM_SMEM);
        cudaFuncSetAttribute(gemm_out_kernel,
                             cudaFuncAttributeMaxDynamicSharedMemorySize, GEMM_SMEM);
        cudaFuncSetAttribute(attn_mma_kernel,
                             cudaFuncAttributeMaxDynamicSharedMemorySize, ATTN_SMEM);
        attr_done = true;
    }

    // Pre-pass: f16 convert + K-perm16 all GEMM operands; cos/sin tables
    {
        int n;
        n = MTOT * DIM / 16;
        prep_kernel<<<(n + 255) / 256, 256>>>(x, xh, n);
        n = DIM * DIM / 16;
        prep_kernel<<<(n + 255) / 256, 256>>>(wq, wqh, n);
        prep_kernel<<<(n + 255) / 256, 256>>>(wo, woh, n);
        n = HKV * HD * DIM / 16;
        prep_kernel<<<(n + 255) / 256, 256>>>(wk, wkh, n);
        prep_kernel<<<(n + 255) / 256, 256>>>(wv, wvh, n);
        n = S_LEN * (HD / 2);
        cs_kernel<<<(n + 255) / 256, 256>>>(freqs);
    }

    // Fused QKV projections + RoPE (mma.sync f16) -> f16 perm16 q/k, f16 v
    gemm_qkv_kernel<<<dim3(24, MTOT / 128), 256, GEMM_SMEM>>>(
        xh, wqh, wkh, wvh, qh, kh, vh);

    // Attention (mma.sync f16 flash) -> f16 perm16 output
    attn_mma_kernel<<<dim3(S_LEN / 128, HQ, BATCH), 256, ATTN_SMEM>>>(
        qh, kh, vh, aoh);

    // Output projection (mma.sync f16) -> fp32
    gemm_out_kernel<<<dim3(DIM / 128, MTOT / 128), 256, GEMM_SMEM>>>(
        aoh, woh, out, DIM, DIM);
}

// round 16
// speedup vs baseline: 7.3151x; 1.0586x over previous
#include <cuda_runtime.h>
#include <cuda_fp16.h>
#include <math_constants.h>
#include <cstdint>

#define BATCH 4
#define S_LEN 1024
#define DIM   2048
#define HQ    16
#define HKV   4
#define HD    128
#define MTOT  (BATCH * S_LEN)   // 4096

// Scratch (allocation-free rule: __device__ globals)
__device__ __half g_qh[MTOT * HQ * HD];    // q, f16 + d-perm16, rope applied
__device__ __half g_kh[MTOT * HKV * HD];   // k, f16 + d-perm16, rope applied
__device__ __half g_vh[MTOT * HKV * HD];   // v, f16 plain
__device__ __half g_xh[MTOT * DIM];        // x, f16 + K-perm16
__device__ __half g_wqh[DIM * DIM];        // wq, f16 + K-perm16
__device__ __half g_wkh[HKV * HD * DIM];   // wk
__device__ __half g_wvh[HKV * HD * DIM];   // wv
__device__ __half g_woh[DIM * DIM];        // wo
__device__ __half g_aoh[MTOT * DIM];       // attn out, f16 + K-perm16
__device__ float  g_ct[S_LEN * HD / 2];    // cos(freqs)
__device__ float  g_st[S_LEN * HD / 2];    // sin(freqs)

// ===========================================================================
// Helpers
// ===========================================================================
__device__ __forceinline__ void cp_async16(uint32_t dst, const void* src) {
    asm volatile("cp.async.cg.shared.global [%0], [%1], 16;\n"
                 :: "r"(dst), "l"(__cvta_generic_to_global(src)));
}
#define CP_COMMIT() asm volatile("cp.async.commit_group;\n" ::: "memory")
#define CP_WAIT0()  asm volatile("cp.async.wait_group 0;\n" ::: "memory")
#define CP_WAIT1()  asm volatile("cp.async.wait_group 1;\n" ::: "memory")

// D += A*B  (m16n8k16 f16, f32 accum)
__device__ __forceinline__ void mma_f16(float* c, const uint32_t* a,
                                        const uint32_t* b) {
    asm volatile(
        "mma.sync.aligned.m16n8k16.row.col.f32.f16.f16.f32 "
        "{%0,%1,%2,%3}, {%4,%5,%6,%7}, {%8,%9}, {%0,%1,%2,%3};"
        : "+f"(c[0]), "+f"(c[1]), "+f"(c[2]), "+f"(c[3])
        : "r"(a[0]), "r"(a[1]), "r"(a[2]), "r"(a[3]), "r"(b[0]), "r"(b[1]));
}

__device__ __forceinline__ void ldsm_x4(uint32_t& r0, uint32_t& r1,
                                        uint32_t& r2, uint32_t& r3,
                                        uint32_t addr) {
    asm volatile("ldmatrix.sync.aligned.m8n8.x4.shared.b16 {%0,%1,%2,%3}, [%4];"
                 : "=r"(r0), "=r"(r1), "=r"(r2), "=r"(r3) : "r"(addr));
}

// Permute a group of 16 floats -> 16 halves:
// new = [0,1,8,9, 2,3,10,11, 4,5,12,13, 6,7,14,15]
__device__ __forceinline__ void perm16_store(__half* dst, float4 a, float4 b,
                                             float4 c, float4 d) {
    __half2 h[8];
    h[0] = __floats2half2_rn(a.x, a.y);
    h[1] = __floats2half2_rn(c.x, c.y);
    h[2] = __floats2half2_rn(a.z, a.w);
    h[3] = __floats2half2_rn(c.z, c.w);
    h[4] = __floats2half2_rn(b.x, b.y);
    h[5] = __floats2half2_rn(d.x, d.y);
    h[6] = __floats2half2_rn(b.z, b.w);
    h[7] = __floats2half2_rn(d.z, d.w);
    *(uint4*)dst       = *(uint4*)&h[0];
    *(uint4*)(dst + 8) = *(uint4*)&h[4];
}

// ===========================================================================
// Pre-pass kernels
// ===========================================================================
__global__ void prep_kernel(const float* __restrict__ in, __half* __restrict__ out,
                            int n16) {
    int i = blockIdx.x * blockDim.x + threadIdx.x;
    if (i >= n16) return;
    const float4* p = (const float4*)(in + (size_t)i * 16);
    perm16_store(out + (size_t)i * 16, p[0], p[1], p[2], p[3]);
}

__global__ void cs_kernel(const float* __restrict__ freqs) {
    int i = blockIdx.x * blockDim.x + threadIdx.x;
    if (i >= S_LEN * (HD / 2)) return;
    float a = freqs[i];
    g_ct[i] = cosf(a);
    g_st[i] = sinf(a);
}

// ===========================================================================
// f16 mma.sync GEMM: C[M,N] = A[M,K] * B[N,K]^T, operands f16 K-perm16.
// CTA 128x128, BK=64 halves, 8 warps (64x32), 3-stage cp.async pipeline.
// SAH=72 (144B rows): ldmatrix m8n8.x4 fragment loads are bank-conflict-free
// (rows land on banks 0,4,...,28). K-perm16 is transparent to ldmatrix: the
// contraction-axis permutation is applied identically to A and B fragments.
// Epilogue modes: 1 = rope+perm16 -> f16 (q/k), 2 = plain -> f16 (v),
//                 3 = plain -> f32 (final output).
// ===========================================================================
#define SAH 72
#define TILE_HALVES (128 * SAH)                 // 9216 halves = 18432 B
#define GEMM_SMEM (6 * TILE_HALVES * 2)         // 110592 B (3 stages x A,B)

__device__ __forceinline__ void load_tile_pair(__half* smA, __half* smB,
                                               const __half* A, const __half* B,
                                               int K, int m0, int n0, int k0,
                                               int tid) {
    const int r  = tid >> 1;            // 0..127
    const int cb = (tid & 1) * 32;      // half col base (0 or 32)
    const __half* asrc = A + (size_t)(m0 + r) * K + k0 + cb;
    const __half* bsrc = B + (size_t)(n0 + r) * K + k0 + cb;
    uint32_t da = (uint32_t)__cvta_generic_to_shared(smA + r * SAH + cb);
    uint32_t db = (uint32_t)__cvta_generic_to_shared(smB + r * SAH + cb);
#pragma unroll
    for (int j = 0; j < 4; j++) {
        cp_async16(da + j * 16, asrc + j * 8);
        cp_async16(db + j * 16, bsrc + j * 8);
    }
}

template <int EPI>
__device__ __forceinline__ void gemm_core(__half* smem, const __half* A,
                                          const __half* B, void* Cout,
                                          int N, int K, int m0, int n0) {
    const int tid = threadIdx.x;
    const int wid = tid >> 5;
    const int lane = tid & 31;
    const int g   = lane >> 2;
    const int tig = lane & 3;
    const int wm = wid >> 2;
    const int wn = wid & 3;

    // ldmatrix lane offsets (in halves, within a tile buffer)
    const int lq = lane >> 3;           // matrix index 0..3
    const int lr = lane & 7;            // row within matrix
    int aoff[4], boff[2];
#pragma unroll
    for (int ma = 0; ma < 4; ma++)
        aoff[ma] = (wm * 64 + ma * 16 + (lq & 1) * 8 + lr) * SAH + (lq >> 1) * 8;
#pragma unroll
    for (int p = 0; p < 2; p++)
        boff[p] = (wn * 32 + p * 16 + (lq >> 1) * 8 + lr) * SAH + (lq & 1) * 8;

    float c[4][4][4];
#pragma unroll
    for (int i = 0; i < 4; i++)
#pragma unroll
        for (int j = 0; j < 4; j++)
#pragma unroll
            for (int q = 0; q < 4; q++) c[i][j][q] = 0.0f;

    const int NK = K >> 6;   // 32 for K=2048

    load_tile_pair(smem, smem + 3 * TILE_HALVES, A, B, K, m0, n0, 0, tid);
    CP_COMMIT();
    load_tile_pair(smem + TILE_HALVES, smem + 4 * TILE_HALVES,
                   A, B, K, m0, n0, 64, tid);
    CP_COMMIT();

    int cur = 0;
    for (int kt = 0; kt < NK; kt++) {
        if (kt < NK - 1) { CP_WAIT1(); } else { CP_WAIT0(); }
        __syncthreads();

        // Prefetch kt+2 into buffer (cur+2)%3 (safe: barrier above guarantees
        // all warps finished reading it at iteration kt-1).
        if (kt + 2 < NK) {
            int pf = (cur >= 1) ? cur - 1 : cur + 2;
            load_tile_pair(smem + pf * TILE_HALVES,
                           smem + (3 + pf) * TILE_HALVES,
                           A, B, K, m0, n0, (kt + 2) * 64, tid);
            CP_COMMIT();
        }

        const uint32_t sa = (uint32_t)__cvta_generic_to_shared(smem + cur * TILE_HALVES);
        const uint32_t sb = (uint32_t)__cvta_generic_to_shared(smem + (3 + cur) * TILE_HALVES);

#pragma unroll
        for (int kk = 0; kk < 4; kk++) {
            uint32_t af[4][4], bf[4][2];
#pragma unroll
            for (int ma = 0; ma < 4; ma++)
                ldsm_x4(af[ma][0], af[ma][1], af[ma][2], af[ma][3],
                        sa + (uint32_t)(aoff[ma] + kk * 16) * 2);
#pragma unroll
            for (int p = 0; p < 2; p++) {
                uint32_t r0, r1, r2, r3;
                ldsm_x4(r0, r1, r2, r3, sb + (uint32_t)(boff[p] + kk * 16) * 2);
                bf[2 * p][0] = r0;     bf[2 * p][1] = r1;
                bf[2 * p + 1][0] = r2; bf[2 * p + 1][1] = r3;
            }
#pragma unroll
            for (int ma = 0; ma < 4; ma++)
#pragma unroll
                for (int nb = 0; nb < 4; nb++)
                    mma_f16(c[ma][nb], af[ma], bf[nb]);
        }
        cur = (cur == 2) ? 0 : cur + 1;
    }

#pragma unroll
    for (int ma = 0; ma < 4; ma++) {
        const int r0 = m0 + wm * 64 + ma * 16 + g;
#pragma unroll
        for (int nb = 0; nb < 4; nb++) {
            const int col = n0 + wn * 32 + nb * 8 + 2 * tig;
            float* cc = c[ma][nb];
            if (EPI == 3) {
                float* C = (float*)Cout;
                *(float2*)&C[(size_t)r0 * N + col] = make_float2(cc[0], cc[1]);
                *(float2*)&C[(size_t)(r0 + 8) * N + col] = make_float2(cc[2], cc[3]);
            } else if (EPI == 2) {
                __half* C = (__half*)Cout;
                *(__half2*)&C[(size_t)r0 * N + col] = __floats2half2_rn(cc[0], cc[1]);
                *(__half2*)&C[(size_t)(r0 + 8) * N + col] = __floats2half2_rn(cc[2], cc[3]);
            } else {
                // rope (fp32) + perm16 + f16 store
                __half* C = (__half*)Cout;
                const int p = (col & 127) >> 1;           // rope pair index
                const int j = (col & 15) >> 1;
                const int off = (col & ~15) + ((j < 4) ? 4 * j : 4 * j - 14);
                const int s0 = r0 & (S_LEN - 1);          // token position
                float c0 = g_ct[s0 * 64 + p],       sn0 = g_st[s0 * 64 + p];
                float c1 = g_ct[(s0 + 8) * 64 + p], sn1 = g_st[(s0 + 8) * 64 + p];
                *(__half2*)&C[(size_t)r0 * N + off] =
                    __floats2half2_rn(cc[0] * c0 - cc[1] * sn0,
                                      cc[0] * sn0 + cc[1] * c0);
                *(__half2*)&C[(size_t)(r0 + 8) * N + off] =
                    __floats2half2_rn(cc[2] * c1 - cc[3] * sn1,
                                      cc[2] * sn1 + cc[3] * c1);
            }
        }
    }
}

// Fused QKV + RoPE: grid.x = 16 (wq) + 4 (wk) + 4 (wv), grid.y = 32 m-tiles.
__global__ void __launch_bounds__(256, 2) gemm_qkv_kernel(
    const __half* __restrict__ x, const __half* __restrict__ wq,
    const __half* __restrict__ wk, const __half* __restrict__ wv,
    __half* __restrict__ q, __half* __restrict__ k, __half* __restrict__ v) {
    extern __shared__ __half smh[];
    const int bx = blockIdx.x;
    const int m0 = blockIdx.y * 128;
    if (bx < 16) {
        gemm_core<1>(smh, x, wq, q, 2048, DIM, m0, bx * 128);
    } else if (bx < 20) {
        gemm_core<1>(smh, x, wk, k, 512, DIM, m0, (bx - 16) * 128);
    } else {
        gemm_core<2>(smh, x, wv, v, 512, DIM, m0, (bx - 20) * 128);
    }
}

__global__ void __launch_bounds__(256, 2) gemm_out_kernel(
    const __half* __restrict__ A, const __half* __restrict__ B,
    float* __restrict__ C, int N, int K) {
    extern __shared__ __half smh[];
    gemm_core<3>(smh, A, B, C, N, K, blockIdx.y * 128, blockIdx.x * 128);
}

// ===========================================================================
// Tensorized flash attention (mma.sync f16, fp32 softmax), causal, GQA.
// CTA = 128 q-rows of one (b, qh). 8 warps x 16-row m-blocks. KV tile 64.
// Inputs already f16: q/k d-perm16 (rope applied), v plain [t][d].
// smem (halves): Qs[128][144], Ks[64][144], VsT[128][82], Ps[8][16][80]
// Output written f16 + K-perm16 straight into g_aoh.
// ===========================================================================
#define QSH 144
#define VTH 82
#define PSH 80
#define ATTN_SMEM ((128 * QSH + 64 * QSH + 128 * VTH + 8 * 16 * PSH) * 2)  // 96768 B

__global__ void __launch_bounds__(256, 1) attn_mma_kernel(
    const __half* __restrict__ q, const __half* __restrict__ k,
    const __half* __restrict__ v, __half* __restrict__ o) {
    extern __shared__ __half smh[];
    __half* Qs  = smh;                   // 128*144
    __half* Ks  = Qs + 128 * QSH;        // 64*144
    __half* VsT = Ks + 64 * QSH;         // 128*82  [d][t-perm16]
    __half* Ps  = VsT + 128 * VTH;       // per-warp 16*80

    const int tid  = threadIdx.x;
    const int lane = tid & 31;
    const int wid  = tid >> 5;
    const int g    = lane >> 2;
    const int tig  = lane & 3;
    const int qt = blockIdx.x;
    const int qh = blockIdx.y;
    const int b  = blockIdx.z;
    const int kh = qh >> 2;
    const int q0 = qt * 128;
    const int wm0 = wid * 16;

    const float scale = 0.08838834764831845f;  // 1/sqrt(128)

    // ---- Load Q tile (already f16 perm16): plain copy ----
    const __half* qp = q + ((size_t)(b * S_LEN + q0)) * (HQ * HD) + qh * HD;
#pragma unroll
    for (int it = 0; it < 4; it++) {
        int gid = it * 256 + tid;
        int row = gid >> 3, gi = gid & 7;
        const uint4* p = (const uint4*)(qp + (size_t)row * (HQ * HD) + gi * 16);
        *(uint4*)&Qs[row * QSH + gi * 16]     = p[0];
        *(uint4*)&Qs[row * QSH + gi * 16 + 8] = p[1];
    }

    float oacc[16][4];
#pragma unroll
    for (int nf = 0; nf < 16; nf++)
#pragma unroll
        for (int j = 0; j < 4; j++) oacc[nf][j] = 0.0f;
    float mi[2] = {-CUDART_INF_F, -CUDART_INF_F};
    float li[2] = {0.0f, 0.0f};

    const int nkt = 2 * qt + 2;
    for (int kt = 0; kt < nkt; kt++) {
        const int t0 = kt * 64;
        __syncthreads();

        // ---- K tile (f16 perm16): plain copy ----
        const __half* kp = k + ((size_t)(b * S_LEN + t0)) * (HKV * HD) + kh * HD;
#pragma unroll
        for (int it = 0; it < 2; it++) {
            int gid = it * 256 + tid;
            int row = gid >> 3, gi = gid & 7;
            const uint4* p = (const uint4*)(kp + (size_t)row * (HKV * HD) + gi * 16);
            *(uint4*)&Ks[row * QSH + gi * 16]     = p[0];
            *(uint4*)&Ks[row * QSH + gi * 16 + 8] = p[1];
        }
        // ---- V tile transposed + t-perm16: VsT[d][perm(t)] ----
        const __half* vp = v + ((size_t)(b * S_LEN + t0)) * (HKV * HD) + kh * HD;
#pragma unroll
        for (int it = 0; it < 8; it++) {
            int idx = it * 256 + tid;          // 2048 quads
            int d = idx & 127;
            int s = idx >> 7;                  // 0..15
            int gi = s >> 2, si = s & 3;
            int tb = 16 * gi;
            __half a0 = vp[(size_t)(tb + 2 * si)     * (HKV * HD) + d];
            __half a1 = vp[(size_t)(tb + 2 * si + 1) * (HKV * HD) + d];
            __half a2 = vp[(size_t)(tb + 2 * si + 8) * (HKV * HD) + d];
            __half a3 = vp[(size_t)(tb + 2 * si + 9) * (HKV * HD) + d];
            __half2* dst = (__half2*)&VsT[d * VTH + tb + 4 * si];
            dst[0] = __halves2half2(a0, a1);
            dst[1] = __halves2half2(a2, a3);
        }
        __syncthreads();

        if (t0 > q0 + wm0 + 15) continue;

        // ---- S = Q K^T (16 x 64 per warp), k = d = 128 -> 8 kk steps ----
        float s[8][4];
#pragma unroll
        for (int nb = 0; nb < 8; nb++)
#pragma unroll
            for (int j = 0; j < 4; j++) s[nb][j] = 0.0f;

#pragma unroll
        for (int kk = 0; kk < 8; kk++) {
            const __half* ap = Qs + (wm0 + g) * QSH + kk * 16 + 4 * tig;
            uint2 lo = *(const uint2*)ap;
            uint2 hi = *(const uint2*)(ap + 8 * QSH);
            uint32_t af[4] = {lo.x, hi.x, lo.y, hi.y};
#pragma unroll
            for (int nb = 0; nb < 8; nb++) {
                const __half* bp = Ks + (nb * 8 + g) * QSH + kk * 16 + 4 * tig;
                uint2 v2 = *(const uint2*)bp;
                uint32_t bf[2] = {v2.x, v2.y};
                mma_f16(s[nb], af, bf);
            }
        }

        // ---- Scale + causal mask ----
        const int row0 = q0 + wm0 + g;
#pragma unroll
        for (int nb = 0; nb < 8; nb++) {
#pragma unroll
            for (int j = 0; j < 4; j++) {
                int col = t0 + nb * 8 + 2 * tig + (j & 1);
                int row = row0 + ((j >= 2) ? 8 : 0);
                float sc = s[nb][j] * scale;
                s[nb][j] = (col > row) ? -1e9f : sc;
            }
        }

        // ---- Online softmax (rows g, g+8 per lane) ----
#pragma unroll
        for (int h = 0; h < 2; h++) {
            float mx = -CUDART_INF_F;
#pragma unroll
            for (int nb = 0; nb < 8; nb++)
                mx = fmaxf(mx, fmaxf(s[nb][2 * h], s[nb][2 * h + 1]));
            mx = fmaxf(mx, __shfl_xor_sync(0xffffffffu, mx, 1));
            mx = fmaxf(mx, __shfl_xor_sync(0xffffffffu, mx, 2));
            float mnew = fmaxf(mi[h], mx);
            float al = __expf(mi[h] - mnew);
            float rs = 0.0f;
#pragma unroll
            for (int nb = 0; nb < 8; nb++) {
                float p0 = __expf(s[nb][2 * h] - mnew);
                float p1 = __expf(s[nb][2 * h + 1] - mnew);
                s[nb][2 * h] = p0;
                s[nb][2 * h + 1] = p1;
                rs += p0 + p1;
            }
            rs += __shfl_xor_sync(0xffffffffu, rs, 1);
            rs += __shfl_xor_sync(0xffffffffu, rs, 2);
            li[h] = li[h] * al + rs;
            mi[h] = mnew;
#pragma unroll
            for (int nf = 0; nf < 16; nf++) {
                oacc[nf][2 * h]     *= al;
                oacc[nf][2 * h + 1] *= al;
            }
        }

        // ---- Store P (f16, t-perm16) to per-warp smem ----
        __half* Pw = Ps + wid * 16 * PSH;
#pragma unroll
        for (int nb = 0; nb < 8; nb++) {
            int off = 16 * (nb >> 1) + 4 * tig + 2 * (nb & 1);
            *(__half2*)&Pw[g * PSH + off] = __floats2half2_rn(s[nb][0], s[nb][1]);
            *(__half2*)&Pw[(g + 8) * PSH + off] = __floats2half2_rn(s[nb][2], s[nb][3]);
        }
        __syncwarp();

        // ---- O += P V  (16 x 128 per warp), k = t = 64 -> 4 kk steps ----
#pragma unroll
        for (int kk = 0; kk < 4; kk++) {
            const __half* ap = Pw + g * PSH + kk * 16 + 4 * tig;
            uint2 lo = *(const uint2*)ap;
            uint2 hi = *(const uint2*)(ap + 8 * PSH);
            uint32_t af[4] = {lo.x, hi.x, lo.y, hi.y};
#pragma unroll
            for (int nf = 0; nf < 16; nf++) {
                // VTH=82 (odd word stride): use two aligned 4-byte loads.
                const __half* bp = VsT + (nf * 8 + g) * VTH + kk * 16 + 4 * tig;
                uint32_t bf[2];
                bf[0] = *(const uint32_t*)bp;
                bf[1] = *(const uint32_t*)(bp + 2);
                mma_f16(oacc[nf], af, bf);
            }
        }
        __syncwarp();
    }

    // ---- Normalize + store f16 K-perm16 (A operand of wo GEMM) ----
    const float inv0 = 1.0f / li[0];
    const float inv1 = 1.0f / li[1];
    __half* ob = o + ((size_t)(b * S_LEN + q0 + wm0 + g)) * (HQ * HD) + qh * HD;
#pragma unroll
    for (int nf = 0; nf < 16; nf++) {
        int off = 16 * (nf >> 1) + 4 * tig + 2 * (nf & 1);
        *(__half2*)&ob[off] = __floats2half2_rn(oacc[nf][0] * inv0, oacc[nf][1] * inv0);
        *(__half2*)&ob[(size_t)8 * (HQ * HD) + off] =
            __floats2half2_rn(oacc[nf][2] * inv1, oacc[nf][3] * inv1);
    }
}

// ---------------------------------------------------------------------------
// Launch
// ---------------------------------------------------------------------------
extern "C" void kernel_launch(void* const* d_in, const int* in_sizes, int n_in,
                              void* d_out, int out_size) {
    const float* x     = (const float*)d_in[0];
    const float* freqs = (const float*)d_in[2];
    const float* wq    = (const float*)d_in[4];
    const float* wk    = (const float*)d_in[5];
    const float* wv    = (const float*)d_in[6];
    const float* wo    = (const float*)d_in[7];
    float* out = (float*)d_out;

    __half *qh, *kh, *vh, *xh, *wqh, *wkh, *wvh, *woh, *aoh;
    cudaGetSymbolAddress((void**)&qh,  g_qh);
    cudaGetSymbolAddress((void**)&kh,  g_kh);
    cudaGetSymbolAddress((void**)&vh,  g_vh);
    cudaGetSymbolAddress((void**)&xh,  g_xh);
    cudaGetSymbolAddress((void**)&wqh, g_wqh);
    cudaGetSymbolAddress((void**)&wkh, g_wkh);
    cudaGetSymbolAddress((void**)&wvh, g_wvh);
    cudaGetSymbolAddress((void**)&woh, g_woh);
    cudaGetSymbolAddress((void**)&aoh, g_aoh);

    static bool attr_done = false;
    if (!attr_done) {
        cudaFuncSetAttribute(gemm_qkv_kernel,
                             cudaFuncAttributeMaxDynamicSharedMemorySize, GEMM_SMEM);
        cudaFuncSetAttribute(gemm_out_kernel,
                             cudaFuncAttributeMaxDynamicSharedMemorySize, GEMM_SMEM);
        cudaFuncSetAttribute(attn_mma_kernel,
                             cudaFuncAttributeMaxDynamicSharedMemorySize, ATTN_SMEM);
        attr_done = true;
    }

    // Pre-pass: f16 convert + K-perm16 all GEMM operands; cos/sin tables
    {
        int n;
        n = MTOT * DIM / 16;
        prep_kernel<<<(n + 255) / 256, 256>>>(x, xh, n);
        n = DIM * DIM / 16;
        prep_kernel<<<(n + 255) / 256, 256>>>(wq, wqh, n);
        prep_kernel<<<(n + 255) / 256, 256>>>(wo, woh, n);
        n = HKV * HD * DIM / 16;
        prep_kernel<<<(n + 255) / 256, 256>>>(wk, wkh, n);
        prep_kernel<<<(n + 255) / 256, 256>>>(wv, wvh, n);
        n = S_LEN * (HD / 2);
        cs_kernel<<<(n + 255) / 256, 256>>>(freqs);
    }

    // Fused QKV projections + RoPE (mma.sync f16) -> f16 perm16 q/k, f16 v
    gemm_qkv_kernel<<<dim3(24, MTOT / 128), 256, GEMM_SMEM>>>(
        xh, wqh, wkh, wvh, qh, kh, vh);

    // Attention (mma.sync f16 flash) -> f16 perm16 output
    attn_mma_kernel<<<dim3(S_LEN / 128, HQ, BATCH), 256, ATTN_SMEM>>>(
        qh, kh, vh, aoh);

    // Output projection (mma.sync f16) -> fp32
    gemm_out_kernel<<<dim3(DIM / 128, MTOT / 128), 256, GEMM_SMEM>>>(
        aoh, woh, out, DIM, DIM);
}